// round 3
// baseline (speedup 1.0000x reference)
#include <cuda_runtime.h>

#define N_NODES 8192
#define N_EDGES 65536
#define IN_DIM 768
#define HIDDEN 4096
#define N_CLASSES 16

// ---- scratch (device globals; ~26 MB total) ----
__device__ float g_deg[N_NODES];
__device__ float g_dinv[N_NODES];
__device__ float g_xa[N_NODES * IN_DIM];          // 25 MB aggregated X
__device__ float g_logits[N_NODES * N_CLASSES];   // 512 KB
__device__ int   g_is64;                          // edge_index dtype flag

// ---- kernel 0: detect edge_index dtype (int32 vs int64) ----
// If int64 (little-endian, values in [0,8192)), every odd 32-bit word is 0.
__global__ void k_detect(const int* __restrict__ ei32) {
    if (threadIdx.x == 0 && blockIdx.x == 0) {
        int any = 0;
        for (int i = 1; i < 2048; i += 2) any |= ei32[i];
        g_is64 = (any == 0) ? 1 : 0;
    }
}

__device__ __forceinline__ int edge_at(const void* ei, int idx) {
    int v;
    if (g_is64) v = (int)((const long long*)ei)[idx];
    else        v = ((const int*)ei)[idx];
    return v & (N_NODES - 1);   // defensive mask; no-op for valid data
}

// ---- kernel 1: deg init (self loop contributes 1) ----
__global__ void k_deg_init() {
    int i = blockIdx.x * blockDim.x + threadIdx.x;
    if (i < N_NODES) g_deg[i] = 1.0f;
}

// ---- kernel 2: indegree accumulation over dst ----
__global__ void k_deg_accum(const void* __restrict__ ei) {
    int e = blockIdx.x * blockDim.x + threadIdx.x;
    if (e < N_EDGES) atomicAdd(&g_deg[edge_at(ei, N_EDGES + e)], 1.0f);
}

// ---- kernel 3: dinv = rsqrt(deg) ----
__global__ void k_dinv() {
    int i = blockIdx.x * blockDim.x + threadIdx.x;
    if (i < N_NODES) g_dinv[i] = rsqrtf(g_deg[i]);
}

// ---- kernel 4: xa = x * dinv^2 (self loop); also zero logits ----
__global__ void k_selfloop(const float* __restrict__ x) {
    int idx = blockIdx.x * blockDim.x + threadIdx.x;   // over N*IN/4 float4s
    const int per_row = IN_DIM / 4;
    if (idx < N_NODES * per_row) {
        int row = idx / per_row;
        float d = g_dinv[row];
        float s = d * d;
        float4 v = reinterpret_cast<const float4*>(x)[idx];
        v.x *= s; v.y *= s; v.z *= s; v.w *= s;
        reinterpret_cast<float4*>(g_xa)[idx] = v;
    }
    if (idx < N_NODES * N_CLASSES / 4) {
        reinterpret_cast<float4*>(g_logits)[idx] = make_float4(0.f, 0.f, 0.f, 0.f);
    }
}

// ---- kernel 5: edge scatter xa[dst] += x[src] * norm (warp per edge) ----
__global__ void k_scatter(const float* __restrict__ x,
                          const void* __restrict__ ei) {
    int warp = threadIdx.x >> 5;
    int lane = threadIdx.x & 31;
    int e = blockIdx.x * 8 + warp;
    if (e >= N_EDGES) return;
    int s = edge_at(ei, e);
    int d = edge_at(ei, N_EDGES + e);
    float nrm = g_dinv[s] * g_dinv[d];
    const float* xs = x + (size_t)s * IN_DIM;
    float* xo = g_xa + (size_t)d * IN_DIM;
    #pragma unroll 6
    for (int j = lane; j < IN_DIM; j += 32) {
        atomicAdd(&xo[j], xs[j] * nrm);
    }
}

// ---- kernel 6: fused h = relu(xa@W1+b1) tile -> partial logits += h_tile @ W2_tile ----
#define BM 128
#define BN 128
#define BK 16
// shared layout (floats): [0,2048) As(16x128 transp), [2048,4096) Bs(16x128),
// [4096,6144) W2s(128x16). Epilogue reuses [0,4096) as a 32x128 h chunk.
__global__ __launch_bounds__(256, 2) void k_gemm_fused(const float* __restrict__ B,   // W1 [768,4096]
                                                       const float* __restrict__ b1,  // [4096]
                                                       const float* __restrict__ W2)  // [4096,16]
{
    __shared__ __align__(16) float smem[6144];
    float* As  = smem;
    float* Bs  = smem + 2048;
    float* W2s = smem + 4096;

    const int bx = blockIdx.x;          // N (hidden) tile: 0..31
    const int by = blockIdx.y;          // M (node) tile: 0..63
    const int tid = threadIdx.x;
    const int tx = tid & 15;
    const int ty = tid >> 4;

    // preload W2 slice [bx*128 .. +128) x 16 into shared (2 float4 per thread)
    {
        int j = tid >> 1;               // 0..127
        int half = tid & 1;             // 0..1
        float4 w = *reinterpret_cast<const float4*>(&W2[(size_t)(bx * BN + j) * N_CLASSES + half * 8]);
        *reinterpret_cast<float4*>(&W2s[j * N_CLASSES + half * 8]) = w;
        w = *reinterpret_cast<const float4*>(&W2[(size_t)(bx * BN + j) * N_CLASSES + half * 8 + 4]);
        *reinterpret_cast<float4*>(&W2s[j * N_CLASSES + half * 8 + 4]) = w;
    }

    const float* A = g_xa;              // [8192, 768]
    float acc[8][8];
    #pragma unroll
    for (int i = 0; i < 8; i++)
        #pragma unroll
        for (int j = 0; j < 8; j++) acc[i][j] = 0.0f;

    for (int kt = 0; kt < IN_DIM / BK; kt++) {
        __syncthreads();
        #pragma unroll
        for (int l = 0; l < 2; l++) {
            int fid = tid + l * 256;
            int ar = fid >> 2;
            int ac4 = fid & 3;
            float4 v = *reinterpret_cast<const float4*>(
                &A[(size_t)(by * BM + ar) * IN_DIM + kt * BK + ac4 * 4]);
            As[(ac4 * 4 + 0) * BM + ar] = v.x;
            As[(ac4 * 4 + 1) * BM + ar] = v.y;
            As[(ac4 * 4 + 2) * BM + ar] = v.z;
            As[(ac4 * 4 + 3) * BM + ar] = v.w;
        }
        #pragma unroll
        for (int l = 0; l < 2; l++) {
            int fid = tid + l * 256;
            int br = fid >> 5;
            int bc4 = fid & 31;
            float4 v = *reinterpret_cast<const float4*>(
                &B[(size_t)(kt * BK + br) * HIDDEN + bx * BN + bc4 * 4]);
            *reinterpret_cast<float4*>(&Bs[br * BN + bc4 * 4]) = v;
        }
        __syncthreads();

        #pragma unroll
        for (int k = 0; k < BK; k++) {
            float a[8], b[8];
            *reinterpret_cast<float4*>(&a[0]) = *reinterpret_cast<float4*>(&As[k * BM + ty * 8]);
            *reinterpret_cast<float4*>(&a[4]) = *reinterpret_cast<float4*>(&As[k * BM + ty * 8 + 4]);
            *reinterpret_cast<float4*>(&b[0]) = *reinterpret_cast<float4*>(&Bs[k * BN + tx * 8]);
            *reinterpret_cast<float4*>(&b[4]) = *reinterpret_cast<float4*>(&Bs[k * BN + tx * 8 + 4]);
            #pragma unroll
            for (int i = 0; i < 8; i++)
                #pragma unroll
                for (int j = 0; j < 8; j++) acc[i][j] += a[i] * b[j];
        }
    }

    // bias + relu in-register
    {
        int col0 = bx * BN + tx * 8;
        float4 bb0 = *reinterpret_cast<const float4*>(&b1[col0]);
        float4 bb1 = *reinterpret_cast<const float4*>(&b1[col0 + 4]);
        #pragma unroll
        for (int i = 0; i < 8; i++) {
            acc[i][0] = fmaxf(acc[i][0] + bb0.x, 0.0f);
            acc[i][1] = fmaxf(acc[i][1] + bb0.y, 0.0f);
            acc[i][2] = fmaxf(acc[i][2] + bb0.z, 0.0f);
            acc[i][3] = fmaxf(acc[i][3] + bb0.w, 0.0f);
            acc[i][4] = fmaxf(acc[i][4] + bb1.x, 0.0f);
            acc[i][5] = fmaxf(acc[i][5] + bb1.y, 0.0f);
            acc[i][6] = fmaxf(acc[i][6] + bb1.z, 0.0f);
            acc[i][7] = fmaxf(acc[i][7] + bb1.w, 0.0f);
        }
    }

    // epilogue: 4 chunks of 32 rows; stage h to shared (swizzled), then h_chunk @ W2s
    float4* chunkf4 = reinterpret_cast<float4*>(smem);   // 32 rows x 32 float4-cols
    const int r2 = tid >> 3;            // 0..31 (row within chunk, pass 2)
    const int c0 = (tid & 7) * 2;       // class pair

    #pragma unroll
    for (int g = 0; g < 4; g++) {
        __syncthreads();                 // As/Bs (or prev chunk) free
        if ((ty >> 2) == g) {
            int tyl = ty & 3;
            #pragma unroll
            for (int i = 0; i < 8; i++) {
                int r = tyl * 8 + i;     // 0..31
                int j4a = 2 * tx;
                int pa = (j4a + 5 * r) & 31;
                int pb = ((j4a + 1) + 5 * r) & 31;
                chunkf4[r * 32 + pa] = make_float4(acc[i][0], acc[i][1], acc[i][2], acc[i][3]);
                chunkf4[r * 32 + pb] = make_float4(acc[i][4], acc[i][5], acc[i][6], acc[i][7]);
            }
        }
        __syncthreads();

        float f0 = 0.0f, f1 = 0.0f;
        #pragma unroll
        for (int j4 = 0; j4 < 32; j4++) {
            float4 hv = chunkf4[r2 * 32 + ((j4 + 5 * r2) & 31)];
            int j = j4 * 4;
            float2 w;
            w = *reinterpret_cast<const float2*>(&W2s[(j + 0) * N_CLASSES + c0]);
            f0 += hv.x * w.x; f1 += hv.x * w.y;
            w = *reinterpret_cast<const float2*>(&W2s[(j + 1) * N_CLASSES + c0]);
            f0 += hv.y * w.x; f1 += hv.y * w.y;
            w = *reinterpret_cast<const float2*>(&W2s[(j + 2) * N_CLASSES + c0]);
            f0 += hv.z * w.x; f1 += hv.z * w.y;
            w = *reinterpret_cast<const float2*>(&W2s[(j + 3) * N_CLASSES + c0]);
            f0 += hv.w * w.x; f1 += hv.w * w.y;
        }
        int row = by * BM + g * 32 + r2;
        atomicAdd(&g_logits[row * N_CLASSES + c0], f0);
        atomicAdd(&g_logits[row * N_CLASSES + c0 + 1], f1);
    }
}

// ---- kernel 7: log_softmax over 16 classes (16 lanes per row) ----
__global__ void k_lsm(const float* __restrict__ b2, float* __restrict__ out) {
    int t = blockIdx.x * blockDim.x + threadIdx.x;   // over N*16
    if (t >= N_NODES * N_CLASSES) return;
    int c = t & 15;
    float v = g_logits[t] + b2[c];
    float m = v;
    #pragma unroll
    for (int k = 8; k > 0; k >>= 1)
        m = fmaxf(m, __shfl_xor_sync(0xffffffffu, m, k, 16));
    float s = __expf(v - m);
    #pragma unroll
    for (int k = 8; k > 0; k >>= 1)
        s += __shfl_xor_sync(0xffffffffu, s, k, 16);
    out[t] = v - m - __logf(s);
}

// ---- eager module load: materialize statics & kernels before harness checkpoints ----
namespace {
struct EagerLoad {
    EagerLoad() {
        void* p = nullptr;
        cudaGetSymbolAddress(&p, g_xa);
        cudaGetSymbolAddress(&p, g_logits);
        cudaGetSymbolAddress(&p, g_deg);
        cudaGetSymbolAddress(&p, g_dinv);
        cudaGetSymbolAddress(&p, g_is64);
        cudaFuncAttributes a;
        cudaFuncGetAttributes(&a, k_detect);
        cudaFuncGetAttributes(&a, k_deg_init);
        cudaFuncGetAttributes(&a, k_deg_accum);
        cudaFuncGetAttributes(&a, k_dinv);
        cudaFuncGetAttributes(&a, k_selfloop);
        cudaFuncGetAttributes(&a, k_scatter);
        cudaFuncGetAttributes(&a, k_gemm_fused);
        cudaFuncGetAttributes(&a, k_lsm);
    }
};
EagerLoad g_eager_load;
}

extern "C" void kernel_launch(void* const* d_in, const int* in_sizes, int n_in,
                              void* d_out, int out_size) {
    const float* x  = (const float*)d_in[0];
    const void*  ei = d_in[1];                 // [2, E], int32 OR int64 (detected)
    const float* W1 = (const float*)d_in[2];
    const float* b1 = (const float*)d_in[3];
    const float* W2 = (const float*)d_in[4];
    const float* b2 = (const float*)d_in[5];
    float* out = (float*)d_out;

    k_detect<<<1, 32>>>((const int*)ei);
    k_deg_init<<<(N_NODES + 255) / 256, 256>>>();
    k_deg_accum<<<(N_EDGES + 255) / 256, 256>>>(ei);
    k_dinv<<<(N_NODES + 255) / 256, 256>>>();
    k_selfloop<<<(N_NODES * (IN_DIM / 4) + 255) / 256, 256>>>(x);
    k_scatter<<<N_EDGES / 8, 256>>>(x, ei);
    k_gemm_fused<<<dim3(HIDDEN / BN, N_NODES / BM), 256>>>(W1, b1, W2);
    k_lsm<<<(N_NODES * N_CLASSES + 255) / 256, 256>>>(b2, out);
}

// round 5
// speedup vs baseline: 2.8454x; 2.8454x over previous
#include <cuda_runtime.h>
#include <cuda_fp16.h>
#include <cstdint>

#define N_NODES 8192
#define N_EDGES 65536
#define IN_DIM 768
#define HIDDEN 4096
#define N_CLASSES 16

// ---- scratch (device globals; ~64 MB total) ----
__device__ float g_deg[N_NODES];
__device__ float g_dinv[N_NODES];
__device__ float g_xa[N_NODES * IN_DIM];          // 25 MB aggregated X (fp32)
__device__ float g_logits[N_NODES * N_CLASSES];   // 512 KB
__device__ int   g_is64;
// fp16 hi/lo splits
__device__ __half g_a_hi[N_NODES * IN_DIM];       // 12.6 MB
__device__ __half g_a_lo[N_NODES * IN_DIM];
__device__ __half g_bt_hi[HIDDEN * IN_DIM];       // 6.3 MB (W1^T)
__device__ __half g_bt_lo[HIDDEN * IN_DIM];

// ============================ PTX helpers (baseline ISA only) ============================
__device__ __forceinline__ uint32_t smem_to_u32(const void* p) {
    uint32_t a;
    asm("{ .reg .u64 t; cvta.to.shared.u64 t, %1; cvt.u32.u64 %0, t; }" : "=r"(a) : "l"(p));
    return a;
}
#define CP_ASYNC16(smem, gptr) \
    asm volatile("cp.async.cg.shared.global [%0], [%1], 16;" :: "r"(smem), "l"(gptr) : "memory")
#define CP_COMMIT() asm volatile("cp.async.commit_group;" ::: "memory")
#define CP_WAIT(n)  asm volatile("cp.async.wait_group %0;" :: "n"(n) : "memory")

__device__ __forceinline__ void ldsm4(uint32_t* r, uint32_t addr) {
    asm volatile("ldmatrix.sync.aligned.m8n8.x4.shared.b16 {%0,%1,%2,%3}, [%4];"
        : "=r"(r[0]), "=r"(r[1]), "=r"(r[2]), "=r"(r[3]) : "r"(addr));
}
__device__ __forceinline__ void mma16816(float* d, const uint32_t* a, const uint32_t* b) {
    asm volatile("mma.sync.aligned.m16n8k16.row.col.f32.f16.f16.f32 "
        "{%0,%1,%2,%3}, {%4,%5,%6,%7}, {%8,%9}, {%0,%1,%2,%3};"
        : "+f"(d[0]), "+f"(d[1]), "+f"(d[2]), "+f"(d[3])
        : "r"(a[0]), "r"(a[1]), "r"(a[2]), "r"(a[3]), "r"(b[0]), "r"(b[1]));
}

// ============================ graph prep ============================
__global__ void k_detect(const int* __restrict__ ei32) {
    if (threadIdx.x == 0 && blockIdx.x == 0) {
        int any = 0;
        for (int i = 1; i < 2048; i += 2) any |= ei32[i];
        g_is64 = (any == 0) ? 1 : 0;
    }
}
__device__ __forceinline__ int edge_at(const void* ei, int idx) {
    int v;
    if (g_is64) v = (int)((const long long*)ei)[idx];
    else        v = ((const int*)ei)[idx];
    return v & (N_NODES - 1);
}
__global__ void k_deg_init() {
    int i = blockIdx.x * blockDim.x + threadIdx.x;
    if (i < N_NODES) g_deg[i] = 1.0f;
}
__global__ void k_deg_accum(const void* __restrict__ ei) {
    int e = blockIdx.x * blockDim.x + threadIdx.x;
    if (e < N_EDGES) atomicAdd(&g_deg[edge_at(ei, N_EDGES + e)], 1.0f);
}
__global__ void k_dinv() {
    int i = blockIdx.x * blockDim.x + threadIdx.x;
    if (i < N_NODES) g_dinv[i] = rsqrtf(g_deg[i]);
}
__global__ void k_selfloop(const float* __restrict__ x) {
    int idx = blockIdx.x * blockDim.x + threadIdx.x;
    const int per_row = IN_DIM / 4;
    if (idx < N_NODES * per_row) {
        int row = idx / per_row;
        float d = g_dinv[row];
        float s = d * d;
        float4 v = reinterpret_cast<const float4*>(x)[idx];
        v.x *= s; v.y *= s; v.z *= s; v.w *= s;
        reinterpret_cast<float4*>(g_xa)[idx] = v;
    }
    if (idx < N_NODES * N_CLASSES / 4) {
        reinterpret_cast<float4*>(g_logits)[idx] = make_float4(0.f, 0.f, 0.f, 0.f);
    }
}
__global__ void k_scatter(const float* __restrict__ x, const void* __restrict__ ei) {
    int warp = threadIdx.x >> 5;
    int lane = threadIdx.x & 31;
    int e = blockIdx.x * 8 + warp;
    if (e >= N_EDGES) return;
    int s = edge_at(ei, e);
    int d = edge_at(ei, N_EDGES + e);
    float nrm = g_dinv[s] * g_dinv[d];
    const float* xs = x + (size_t)s * IN_DIM;
    float* xo = g_xa + (size_t)d * IN_DIM;
    #pragma unroll 6
    for (int j = lane; j < IN_DIM; j += 32) {
        atomicAdd(&xo[j], xs[j] * nrm);
    }
}

// ---- fp16 hi/lo split of aggregated A ----
__global__ void k_prep_a() {
    int i = blockIdx.x * blockDim.x + threadIdx.x;   // over pairs
    if (i >= N_NODES * IN_DIM / 2) return;
    float2 v = reinterpret_cast<const float2*>(g_xa)[i];
    __half h0 = __float2half(v.x);
    __half h1 = __float2half(v.y);
    __half l0 = __float2half(v.x - __half2float(h0));
    __half l1 = __float2half(v.y - __half2float(h1));
    reinterpret_cast<__half2*>(g_a_hi)[i] = __halves2half2(h0, h1);
    reinterpret_cast<__half2*>(g_a_lo)[i] = __halves2half2(l0, l1);
}
// ---- W1 [768][4096] -> transposed fp16 hi/lo [4096][768] ----
__global__ void k_prep_bt(const float* __restrict__ W1) {
    __shared__ float t[32][33];
    int bn = blockIdx.x;                 // 4096/32
    int bk = blockIdx.y;                 // 768/32
    int x = threadIdx.x & 31, y = threadIdx.x >> 5;   // 32x8
    #pragma unroll
    for (int r = 0; r < 4; r++) {
        int kl = y + r * 8;
        t[kl][x] = W1[(size_t)(bk * 32 + kl) * HIDDEN + bn * 32 + x];
    }
    __syncthreads();
    #pragma unroll
    for (int r = 0; r < 4; r++) {
        int nl = y + r * 8;
        float v = t[x][nl];              // = W1[bk*32+x][bn*32+nl]
        __half h = __float2half(v);
        __half l = __float2half(v - __half2float(h));
        size_t o = (size_t)(bn * 32 + nl) * IN_DIM + bk * 32 + x;
        g_bt_hi[o] = h;
        g_bt_lo[o] = l;
    }
}

// ============================ HMMA GEMM (mma.sync, 3-term fp16) ============================
// C[8192,4096] over effective K' = 3*768: seg0 Ah*Bh, seg1 Al*Bh, seg2 Ah*Bl.
// Block tile 128x128, 8 warps (2M x 4N), warp tile 64x32, k-chunk 32, 4-stage cp.async.
#define NCHUNK 72
#define STAGE_B 16384
#define H_STRIDE 130
#define W2S_OFF 66560               // 128*130*4 (h buffer / stage union)
#define B1S_OFF (W2S_OFF + 8192)
#define SMEM_TOTAL (B1S_OFF + 512)

__global__ __launch_bounds__(256, 2) void k_gemm_mma(const float* __restrict__ b1,
                                                     const float* __restrict__ W2) {
    extern __shared__ __align__(128) char smem[];
    const uint32_t sb = smem_to_u32(smem);
    const int tid = threadIdx.x, lane = tid & 31, wid = tid >> 5;
    const int wm = wid & 1, wn = wid >> 1;
    const int bx = blockIdx.x, by = blockIdx.y;

    // stage W2 slice (128x16 f32) + b1 slice (128 f32)
    {
        const float4* s = reinterpret_cast<const float4*>(W2 + (size_t)bx * 128 * N_CLASSES);
        float4* d = reinterpret_cast<float4*>(smem + W2S_OFF);
        #pragma unroll
        for (int i = tid; i < 512; i += 256) d[i] = s[i];
        if (tid < 128) reinterpret_cast<float*>(smem + B1S_OFF)[tid] = b1[bx * 128 + tid];
    }

    float c[4][4][4];
    #pragma unroll
    for (int mi = 0; mi < 4; mi++)
        #pragma unroll
        for (int ni = 0; ni < 4; ni++)
            #pragma unroll
            for (int q = 0; q < 4; q++) c[mi][ni][q] = 0.0f;

    auto load_stage = [&](int ch) {
        int buf = ch & 3;
        int seg = ch / 24;
        int kk = (ch % 24) * 32;
        const __half* Ap = (seg == 1) ? g_a_lo : g_a_hi;
        const __half* Bp = (seg == 2) ? g_bt_lo : g_bt_hi;
        #pragma unroll
        for (int i = 0; i < 2; i++) {
            int idx = tid + i * 256;
            int row = idx >> 2, chk = idx & 3;
            const __half* g = Ap + (size_t)(by * 128 + row) * IN_DIM + kk + chk * 8;
            uint32_t s = sb + buf * STAGE_B + row * 64 + ((chk ^ (row & 3)) << 4);
            CP_ASYNC16(s, g);
        }
        #pragma unroll
        for (int i = 0; i < 2; i++) {
            int idx = tid + i * 256;
            int row = idx >> 2, chk = idx & 3;
            const __half* g = Bp + (size_t)(bx * 128 + row) * IN_DIM + kk + chk * 8;
            uint32_t s = sb + buf * STAGE_B + 8192 + row * 64 + ((chk ^ (row & 3)) << 4);
            CP_ASYNC16(s, g);
        }
        CP_COMMIT();
    };

    load_stage(0); load_stage(1); load_stage(2);

    for (int ch = 0; ch < NCHUNK; ch++) {
        if (ch + 3 < NCHUNK) { CP_WAIT(2); } else { CP_WAIT(0); }
        __syncthreads();
        if (ch + 3 < NCHUNK) load_stage(ch + 3);

        uint32_t aB = sb + (ch & 3) * STAGE_B;
        uint32_t bB = aB + 8192;
        #pragma unroll
        for (int kk = 0; kk < 2; kk++) {
            uint32_t a[4][4], bfr[4][2];
            int arow = wm * 64 + (lane & 15);
            int akc = kk * 2 + (lane >> 4);
            #pragma unroll
            for (int mi = 0; mi < 4; mi++) {
                int row = arow + mi * 16;
                ldsm4(a[mi], aB + row * 64 + ((akc ^ (row & 3)) << 4));
            }
            int bnl = (lane & 7) + ((lane >> 4) << 3);
            int bkc = kk * 2 + ((lane >> 3) & 1);
            #pragma unroll
            for (int nn = 0; nn < 2; nn++) {
                int n = wn * 32 + nn * 16 + bnl;
                uint32_t t[4];
                ldsm4(t, bB + n * 64 + ((bkc ^ (n & 3)) << 4));
                bfr[nn * 2][0] = t[0]; bfr[nn * 2][1] = t[1];
                bfr[nn * 2 + 1][0] = t[2]; bfr[nn * 2 + 1][1] = t[3];
            }
            #pragma unroll
            for (int mi = 0; mi < 4; mi++)
                #pragma unroll
                for (int ni = 0; ni < 4; ni++)
                    mma16816(c[mi][ni], a[mi], bfr[ni]);
        }
    }

    // epilogue: stage h (=C) to smem, then h @ W2 slice -> atomic logits
    __syncthreads();
    float* h = reinterpret_cast<float*>(smem);
    const float* b1s = reinterpret_cast<const float*>(smem + B1S_OFF);
    #pragma unroll
    for (int mi = 0; mi < 4; mi++) {
        int r0 = wm * 64 + mi * 16 + (lane >> 2);
        #pragma unroll
        for (int ni = 0; ni < 4; ni++) {
            int n = wn * 32 + ni * 8 + (lane & 3) * 2;
            *reinterpret_cast<float2*>(&h[r0 * H_STRIDE + n]) =
                make_float2(c[mi][ni][0], c[mi][ni][1]);
            *reinterpret_cast<float2*>(&h[(r0 + 8) * H_STRIDE + n]) =
                make_float2(c[mi][ni][2], c[mi][ni][3]);
        }
    }
    __syncthreads();
    {
        int r = tid >> 1;
        int cg = (tid & 1) * 8;
        const float* w2s = reinterpret_cast<const float*>(smem + W2S_OFF);
        float acc[8];
        #pragma unroll
        for (int q = 0; q < 8; q++) acc[q] = 0.0f;
        #pragma unroll 4
        for (int n = 0; n < 128; n++) {
            float hv = fmaxf(h[r * H_STRIDE + n] + b1s[n], 0.0f);
            const float4* w = reinterpret_cast<const float4*>(w2s + n * N_CLASSES + cg);
            float4 w0 = w[0], w1 = w[1];
            acc[0] += hv * w0.x; acc[1] += hv * w0.y;
            acc[2] += hv * w0.z; acc[3] += hv * w0.w;
            acc[4] += hv * w1.x; acc[5] += hv * w1.y;
            acc[6] += hv * w1.z; acc[7] += hv * w1.w;
        }
        float* lg = &g_logits[(by * 128 + r) * N_CLASSES + cg];
        #pragma unroll
        for (int q = 0; q < 8; q++) atomicAdd(&lg[q], acc[q]);
    }
}

// ---- log_softmax over 16 classes ----
__global__ void k_lsm(const float* __restrict__ b2, float* __restrict__ out) {
    int t = blockIdx.x * blockDim.x + threadIdx.x;
    if (t >= N_NODES * N_CLASSES) return;
    int c = t & 15;
    float v = g_logits[t] + b2[c];
    float m = v;
    #pragma unroll
    for (int k = 8; k > 0; k >>= 1)
        m = fmaxf(m, __shfl_xor_sync(0xffffffffu, m, k, 16));
    float s = __expf(v - m);
    #pragma unroll
    for (int k = 8; k > 0; k >>= 1)
        s += __shfl_xor_sync(0xffffffffu, s, k, 16);
    out[t] = v - m - __logf(s);
}

// ---- eager module load ----
namespace {
struct EagerLoad {
    EagerLoad() {
        void* p = nullptr;
        cudaGetSymbolAddress(&p, g_xa);
        cudaGetSymbolAddress(&p, g_logits);
        cudaGetSymbolAddress(&p, g_deg);
        cudaGetSymbolAddress(&p, g_dinv);
        cudaGetSymbolAddress(&p, g_is64);
        cudaGetSymbolAddress(&p, g_a_hi);
        cudaGetSymbolAddress(&p, g_a_lo);
        cudaGetSymbolAddress(&p, g_bt_hi);
        cudaGetSymbolAddress(&p, g_bt_lo);
        cudaFuncAttributes a;
        cudaFuncGetAttributes(&a, k_detect);
        cudaFuncGetAttributes(&a, k_deg_init);
        cudaFuncGetAttributes(&a, k_deg_accum);
        cudaFuncGetAttributes(&a, k_dinv);
        cudaFuncGetAttributes(&a, k_selfloop);
        cudaFuncGetAttributes(&a, k_scatter);
        cudaFuncGetAttributes(&a, k_prep_a);
        cudaFuncGetAttributes(&a, k_prep_bt);
        cudaFuncGetAttributes(&a, k_gemm_mma);
        cudaFuncGetAttributes(&a, k_lsm);
        cudaFuncSetAttribute(k_gemm_mma, cudaFuncAttributeMaxDynamicSharedMemorySize, SMEM_TOTAL);
    }
};
EagerLoad g_eager_load;
}

extern "C" void kernel_launch(void* const* d_in, const int* in_sizes, int n_in,
                              void* d_out, int out_size) {
    const float* x  = (const float*)d_in[0];
    const void*  ei = d_in[1];                 // [2, E], int32 OR int64 (detected)
    const float* W1 = (const float*)d_in[2];
    const float* b1 = (const float*)d_in[3];
    const float* W2 = (const float*)d_in[4];
    const float* b2 = (const float*)d_in[5];
    float* out = (float*)d_out;

    k_detect<<<1, 32>>>((const int*)ei);
    k_deg_init<<<(N_NODES + 255) / 256, 256>>>();
    k_deg_accum<<<(N_EDGES + 255) / 256, 256>>>(ei);
    k_dinv<<<(N_NODES + 255) / 256, 256>>>();
    k_selfloop<<<(N_NODES * (IN_DIM / 4) + 255) / 256, 256>>>(x);
    k_scatter<<<N_EDGES / 8, 256>>>(x, ei);
    k_prep_a<<<(N_NODES * IN_DIM / 2 + 255) / 256, 256>>>();
    k_prep_bt<<<dim3(HIDDEN / 32, IN_DIM / 32), 256>>>(W1);

    cudaFuncSetAttribute(k_gemm_mma, cudaFuncAttributeMaxDynamicSharedMemorySize, SMEM_TOTAL);
    k_gemm_mma<<<dim3(HIDDEN / 128, N_NODES / 128), 256, SMEM_TOTAL>>>(b1, W2);
    k_lsm<<<(N_NODES * N_CLASSES + 255) / 256, 256>>>(b2, out);
}

// round 6
// speedup vs baseline: 4.0325x; 1.4172x over previous
#include <cuda_runtime.h>
#include <cuda_fp16.h>
#include <cstdint>

#define N_NODES 8192
#define N_EDGES 65536
#define IN_DIM 768
#define HIDDEN 4096
#define N_CLASSES 16

// ---- scratch (device globals) ----
__device__ float g_dinv[N_NODES];
__device__ float g_logits[N_NODES * N_CLASSES];   // 512 KB
__device__ int   g_is64;
__device__ int   g_cnt[N_NODES];
__device__ int   g_off[N_NODES + 1];
__device__ int   g_cursor[N_NODES];
__device__ int   g_csr_src[N_EDGES];
// fp16 hi/lo splits
__device__ __half g_a_hi[N_NODES * IN_DIM];       // 12.6 MB
__device__ __half g_a_lo[N_NODES * IN_DIM];
__device__ __half g_bt_hi[HIDDEN * IN_DIM];       // 6.3 MB (W1^T)
__device__ __half g_bt_lo[HIDDEN * IN_DIM];

// ============================ PTX helpers (baseline ISA only) ============================
__device__ __forceinline__ uint32_t smem_to_u32(const void* p) {
    uint32_t a;
    asm("{ .reg .u64 t; cvta.to.shared.u64 t, %1; cvt.u32.u64 %0, t; }" : "=r"(a) : "l"(p));
    return a;
}
#define CP_ASYNC16(smem, gptr) \
    asm volatile("cp.async.cg.shared.global [%0], [%1], 16;" :: "r"(smem), "l"(gptr) : "memory")
#define CP_COMMIT() asm volatile("cp.async.commit_group;" ::: "memory")
#define CP_WAIT(n)  asm volatile("cp.async.wait_group %0;" :: "n"(n) : "memory")

__device__ __forceinline__ void ldsm4(uint32_t* r, uint32_t addr) {
    asm volatile("ldmatrix.sync.aligned.m8n8.x4.shared.b16 {%0,%1,%2,%3}, [%4];"
        : "=r"(r[0]), "=r"(r[1]), "=r"(r[2]), "=r"(r[3]) : "r"(addr));
}
__device__ __forceinline__ void mma16816(float* d, const uint32_t* a, const uint32_t* b) {
    asm volatile("mma.sync.aligned.m16n8k16.row.col.f32.f16.f16.f32 "
        "{%0,%1,%2,%3}, {%4,%5,%6,%7}, {%8,%9}, {%0,%1,%2,%3};"
        : "+f"(d[0]), "+f"(d[1]), "+f"(d[2]), "+f"(d[3])
        : "r"(a[0]), "r"(a[1]), "r"(a[2]), "r"(a[3]), "r"(b[0]), "r"(b[1]));
}

// ============================ dtype detect / CSR build ============================
__global__ void k_detect(const int* __restrict__ ei32) {
    __shared__ int s_any[256];
    int any = 0;
    #pragma unroll
    for (int r = 0; r < 4; r++) {
        int i = 1 + 2 * (threadIdx.x + 256 * r);
        any |= ei32[i];
    }
    s_any[threadIdx.x] = any;
    __syncthreads();
    for (int o = 128; o > 0; o >>= 1) {
        if (threadIdx.x < o) s_any[threadIdx.x] |= s_any[threadIdx.x + o];
        __syncthreads();
    }
    if (threadIdx.x == 0) g_is64 = (s_any[0] == 0) ? 1 : 0;
}
__device__ __forceinline__ int edge_at(const void* ei, int idx) {
    int v;
    if (g_is64) v = (int)((const long long*)ei)[idx];
    else        v = ((const int*)ei)[idx];
    return v & (N_NODES - 1);
}
__global__ void k_zero() {
    int i = blockIdx.x * blockDim.x + threadIdx.x;
    if (i < N_NODES * N_CLASSES / 4)
        reinterpret_cast<float4*>(g_logits)[i] = make_float4(0.f, 0.f, 0.f, 0.f);
    if (i < N_NODES / 4)
        reinterpret_cast<int4*>(g_cnt)[i] = make_int4(0, 0, 0, 0);
}
__global__ void k_hist(const void* __restrict__ ei) {
    int e = blockIdx.x * blockDim.x + threadIdx.x;
    if (e < N_EDGES) atomicAdd(&g_cnt[edge_at(ei, N_EDGES + e)], 1);
}
// single block 1024 threads: scan counts -> offsets, cursor; dinv = rsqrt(cnt+1)
__global__ __launch_bounds__(1024) void k_scan() {
    __shared__ int part[1024];
    int t = threadIdx.x;
    int base = t * 8;
    int v[8];
    int s = 0;
    #pragma unroll
    for (int i = 0; i < 8; i++) { v[i] = g_cnt[base + i]; s += v[i]; }
    part[t] = s;
    __syncthreads();
    for (int o = 1; o < 1024; o <<= 1) {
        int x = (t >= o) ? part[t - o] : 0;
        __syncthreads();
        part[t] += x;
        __syncthreads();
    }
    int run = part[t] - s;   // exclusive prefix
    #pragma unroll
    for (int i = 0; i < 8; i++) {
        g_off[base + i] = run;
        g_cursor[base + i] = run;
        g_dinv[base + i] = rsqrtf((float)(v[i] + 1));
        run += v[i];
    }
    if (t == 1023) g_off[N_NODES] = run;
}
__global__ void k_fill(const void* __restrict__ ei) {
    int e = blockIdx.x * blockDim.x + threadIdx.x;
    if (e >= N_EDGES) return;
    int s = edge_at(ei, e);
    int d = edge_at(ei, N_EDGES + e);
    int pos = atomicAdd(&g_cursor[d], 1);
    g_csr_src[pos] = s;
}

// ---- gather aggregation (warp per node) + fp16 hi/lo split write ----
__global__ __launch_bounds__(256) void k_gather(const float* __restrict__ x) {
    int v = blockIdx.x * 8 + (threadIdx.x >> 5);
    int lane = threadIdx.x & 31;
    float dv = g_dinv[v];
    const float4* xv = reinterpret_cast<const float4*>(x + (size_t)v * IN_DIM);
    float4 acc[6];
    float sw = dv * dv;
    #pragma unroll
    for (int t = 0; t < 6; t++) {
        float4 a = xv[lane + 32 * t];
        acc[t].x = a.x * sw; acc[t].y = a.y * sw;
        acc[t].z = a.z * sw; acc[t].w = a.w * sw;
    }
    int e0 = g_off[v], e1 = g_off[v + 1];
    for (int p = e0; p < e1; p++) {
        int s = g_csr_src[p];
        float w = g_dinv[s] * dv;
        const float4* xs = reinterpret_cast<const float4*>(x + (size_t)s * IN_DIM);
        #pragma unroll
        for (int t = 0; t < 6; t++) {
            float4 a = xs[lane + 32 * t];
            acc[t].x += a.x * w; acc[t].y += a.y * w;
            acc[t].z += a.z * w; acc[t].w += a.w * w;
        }
    }
    #pragma unroll
    for (int t = 0; t < 6; t++) {
        int eb = v * IN_DIM + lane * 4 + 128 * t;
        float f[4] = {acc[t].x, acc[t].y, acc[t].z, acc[t].w};
        __half h[4], l[4];
        #pragma unroll
        for (int i = 0; i < 4; i++) {
            h[i] = __float2half(f[i]);
            l[i] = __float2half(f[i] - __half2float(h[i]));
        }
        __half2 h01 = __halves2half2(h[0], h[1]), h23 = __halves2half2(h[2], h[3]);
        __half2 l01 = __halves2half2(l[0], l[1]), l23 = __halves2half2(l[2], l[3]);
        uint2 hp = make_uint2(*(uint32_t*)&h01, *(uint32_t*)&h23);
        uint2 lp = make_uint2(*(uint32_t*)&l01, *(uint32_t*)&l23);
        *reinterpret_cast<uint2*>(g_a_hi + eb) = hp;
        *reinterpret_cast<uint2*>(g_a_lo + eb) = lp;
    }
}

// ---- W1 [768][4096] -> transposed fp16 hi/lo [4096][768] ----
__global__ void k_prep_bt(const float* __restrict__ W1) {
    __shared__ float t[32][33];
    int bn = blockIdx.x;
    int bk = blockIdx.y;
    int x = threadIdx.x & 31, y = threadIdx.x >> 5;
    #pragma unroll
    for (int r = 0; r < 4; r++) {
        int kl = y + r * 8;
        t[kl][x] = W1[(size_t)(bk * 32 + kl) * HIDDEN + bn * 32 + x];
    }
    __syncthreads();
    #pragma unroll
    for (int r = 0; r < 4; r++) {
        int nl = y + r * 8;
        float v = t[x][nl];
        __half h = __float2half(v);
        __half l = __float2half(v - __half2float(h));
        size_t o = (size_t)(bn * 32 + nl) * IN_DIM + bk * 32 + x;
        g_bt_hi[o] = h;
        g_bt_lo[o] = l;
    }
}

// ============================ HMMA GEMM (shared-tile 3-term fp16) ============================
// Per 32-wide k-chunk, stage {Ah, Al, Bh, Bl} (32KB) once; run AhBh + AhBl + AlBh.
// Block tile 128x128, 8 warps (2M x 4N), warp tile 64x32, 3-stage cp.async pipeline.
#define KCHUNK 24
#define STAGE_B 32768
#define H_STRIDE 130
#define W2S_OFF 98304
#define B1S_OFF (W2S_OFF + 8192)
#define SMEM_TOTAL (B1S_OFF + 512)

__global__ __launch_bounds__(256, 2) void k_gemm_mma(const float* __restrict__ b1,
                                                     const float* __restrict__ W2) {
    extern __shared__ __align__(128) char smem[];
    const uint32_t sb = smem_to_u32(smem);
    const int tid = threadIdx.x, lane = tid & 31, wid = tid >> 5;
    const int wm = wid & 1, wn = wid >> 1;
    const int bx = blockIdx.x, by = blockIdx.y;

    // stage W2 slice (128x16 f32) + b1 slice (128 f32)
    {
        const float4* s = reinterpret_cast<const float4*>(W2 + (size_t)bx * 128 * N_CLASSES);
        float4* d = reinterpret_cast<float4*>(smem + W2S_OFF);
        #pragma unroll
        for (int i = tid; i < 512; i += 256) d[i] = s[i];
        if (tid < 128) reinterpret_cast<float*>(smem + B1S_OFF)[tid] = b1[bx * 128 + tid];
    }

    float c[4][4][4];
    #pragma unroll
    for (int mi = 0; mi < 4; mi++)
        #pragma unroll
        for (int ni = 0; ni < 4; ni++)
            #pragma unroll
            for (int q = 0; q < 4; q++) c[mi][ni][q] = 0.0f;

    const int row_half = tid >> 2;       // 0..63
    const int chk = tid & 3;
    const int arow_g = by * 128;
    const int brow_g = bx * 128;

    auto load_stage = [&](int ch) {
        int buf = ch - (ch / 3) * 3;     // ch % 3
        int kk = ch * 32;
        uint32_t sbase = sb + buf * STAGE_B;
        #pragma unroll
        for (int half = 0; half < 2; half++) {
            int row = row_half + half * 64;
            uint32_t soff = row * 64 + ((chk ^ (row & 3)) << 4);
            size_t goff = (size_t)row * IN_DIM + kk + chk * 8;
            CP_ASYNC16(sbase +     0 + soff, g_a_hi  + (size_t)arow_g * IN_DIM + goff);
            CP_ASYNC16(sbase +  8192 + soff, g_a_lo  + (size_t)arow_g * IN_DIM + goff);
            CP_ASYNC16(sbase + 16384 + soff, g_bt_hi + (size_t)brow_g * IN_DIM + goff);
            CP_ASYNC16(sbase + 24576 + soff, g_bt_lo + (size_t)brow_g * IN_DIM + goff);
        }
        CP_COMMIT();
    };

    load_stage(0);
    load_stage(1);

    for (int ch = 0; ch < KCHUNK; ch++) {
        if (ch + 2 < KCHUNK) { CP_WAIT(1); } else { CP_WAIT(0); }
        __syncthreads();
        if (ch + 2 < KCHUNK) load_stage(ch + 2);

        int buf = ch - (ch / 3) * 3;
        uint32_t aHB = sb + buf * STAGE_B;
        uint32_t aLB = aHB + 8192;
        uint32_t bHB = aHB + 16384;
        uint32_t bLB = aHB + 24576;

        #pragma unroll
        for (int kk = 0; kk < 2; kk++) {
            uint32_t a[4][4], bh[4][2], bl[4][2];
            int arow = wm * 64 + (lane & 15);
            int akc = kk * 2 + (lane >> 4);
            #pragma unroll
            for (int mi = 0; mi < 4; mi++) {
                int row = arow + mi * 16;
                ldsm4(a[mi], aHB + row * 64 + ((akc ^ (row & 3)) << 4));
            }
            int bnl = (lane & 7) + ((lane >> 4) << 3);
            int bkc = kk * 2 + ((lane >> 3) & 1);
            #pragma unroll
            for (int nn = 0; nn < 2; nn++) {
                int n = wn * 32 + nn * 16 + bnl;
                uint32_t soff = n * 64 + ((bkc ^ (n & 3)) << 4);
                uint32_t t[4];
                ldsm4(t, bHB + soff);
                bh[nn * 2][0] = t[0]; bh[nn * 2][1] = t[1];
                bh[nn * 2 + 1][0] = t[2]; bh[nn * 2 + 1][1] = t[3];
                ldsm4(t, bLB + soff);
                bl[nn * 2][0] = t[0]; bl[nn * 2][1] = t[1];
                bl[nn * 2 + 1][0] = t[2]; bl[nn * 2 + 1][1] = t[3];
            }
            // Ah*Bh + Ah*Bl
            #pragma unroll
            for (int mi = 0; mi < 4; mi++)
                #pragma unroll
                for (int ni = 0; ni < 4; ni++) {
                    mma16816(c[mi][ni], a[mi], bh[ni]);
                    mma16816(c[mi][ni], a[mi], bl[ni]);
                }
            // reuse a-regs for Al, then Al*Bh
            #pragma unroll
            for (int mi = 0; mi < 4; mi++) {
                int row = arow + mi * 16;
                ldsm4(a[mi], aLB + row * 64 + ((akc ^ (row & 3)) << 4));
            }
            #pragma unroll
            for (int mi = 0; mi < 4; mi++)
                #pragma unroll
                for (int ni = 0; ni < 4; ni++)
                    mma16816(c[mi][ni], a[mi], bh[ni]);
        }
    }

    // epilogue: stage h to smem, then h @ W2 slice -> atomic logits
    __syncthreads();
    float* h = reinterpret_cast<float*>(smem);
    const float* b1s = reinterpret_cast<const float*>(smem + B1S_OFF);
    #pragma unroll
    for (int mi = 0; mi < 4; mi++) {
        int r0 = wm * 64 + mi * 16 + (lane >> 2);
        #pragma unroll
        for (int ni = 0; ni < 4; ni++) {
            int n = wn * 32 + ni * 8 + (lane & 3) * 2;
            *reinterpret_cast<float2*>(&h[r0 * H_STRIDE + n]) =
                make_float2(c[mi][ni][0], c[mi][ni][1]);
            *reinterpret_cast<float2*>(&h[(r0 + 8) * H_STRIDE + n]) =
                make_float2(c[mi][ni][2], c[mi][ni][3]);
        }
    }
    __syncthreads();
    {
        int r = tid >> 1;
        int cg = (tid & 1) * 8;
        const float* w2s = reinterpret_cast<const float*>(smem + W2S_OFF);
        float acc[8];
        #pragma unroll
        for (int q = 0; q < 8; q++) acc[q] = 0.0f;
        #pragma unroll 4
        for (int n = 0; n < 128; n++) {
            float hv = fmaxf(h[r * H_STRIDE + n] + b1s[n], 0.0f);
            const float4* w = reinterpret_cast<const float4*>(w2s + n * N_CLASSES + cg);
            float4 w0 = w[0], w1 = w[1];
            acc[0] += hv * w0.x; acc[1] += hv * w0.y;
            acc[2] += hv * w0.z; acc[3] += hv * w0.w;
            acc[4] += hv * w1.x; acc[5] += hv * w1.y;
            acc[6] += hv * w1.z; acc[7] += hv * w1.w;
        }
        float* lg = &g_logits[(by * 128 + r) * N_CLASSES + cg];
        #pragma unroll
        for (int q = 0; q < 8; q++) atomicAdd(&lg[q], acc[q]);
    }
}

// ---- log_softmax over 16 classes ----
__global__ void k_lsm(const float* __restrict__ b2, float* __restrict__ out) {
    int t = blockIdx.x * blockDim.x + threadIdx.x;
    if (t >= N_NODES * N_CLASSES) return;
    int c = t & 15;
    float v = g_logits[t] + b2[c];
    float m = v;
    #pragma unroll
    for (int k = 8; k > 0; k >>= 1)
        m = fmaxf(m, __shfl_xor_sync(0xffffffffu, m, k, 16));
    float s = __expf(v - m);
    #pragma unroll
    for (int k = 8; k > 0; k >>= 1)
        s += __shfl_xor_sync(0xffffffffu, s, k, 16);
    out[t] = v - m - __logf(s);
}

// ---- eager module load ----
namespace {
struct EagerLoad {
    EagerLoad() {
        void* p = nullptr;
        cudaGetSymbolAddress(&p, g_logits);
        cudaGetSymbolAddress(&p, g_dinv);
        cudaGetSymbolAddress(&p, g_is64);
        cudaGetSymbolAddress(&p, g_cnt);
        cudaGetSymbolAddress(&p, g_off);
        cudaGetSymbolAddress(&p, g_cursor);
        cudaGetSymbolAddress(&p, g_csr_src);
        cudaGetSymbolAddress(&p, g_a_hi);
        cudaGetSymbolAddress(&p, g_a_lo);
        cudaGetSymbolAddress(&p, g_bt_hi);
        cudaGetSymbolAddress(&p, g_bt_lo);
        cudaFuncAttributes a;
        cudaFuncGetAttributes(&a, k_detect);
        cudaFuncGetAttributes(&a, k_zero);
        cudaFuncGetAttributes(&a, k_hist);
        cudaFuncGetAttributes(&a, k_scan);
        cudaFuncGetAttributes(&a, k_fill);
        cudaFuncGetAttributes(&a, k_gather);
        cudaFuncGetAttributes(&a, k_prep_bt);
        cudaFuncGetAttributes(&a, k_gemm_mma);
        cudaFuncGetAttributes(&a, k_lsm);
        cudaFuncSetAttribute(k_gemm_mma, cudaFuncAttributeMaxDynamicSharedMemorySize, SMEM_TOTAL);
    }
};
EagerLoad g_eager_load;
}

extern "C" void kernel_launch(void* const* d_in, const int* in_sizes, int n_in,
                              void* d_out, int out_size) {
    const float* x  = (const float*)d_in[0];
    const void*  ei = d_in[1];                 // [2, E], int32 OR int64 (detected)
    const float* W1 = (const float*)d_in[2];
    const float* b1 = (const float*)d_in[3];
    const float* W2 = (const float*)d_in[4];
    const float* b2 = (const float*)d_in[5];
    float* out = (float*)d_out;

    k_detect<<<1, 256>>>((const int*)ei);
    k_zero<<<(N_NODES * N_CLASSES / 4 + 255) / 256, 256>>>();
    k_hist<<<(N_EDGES + 255) / 256, 256>>>(ei);
    k_scan<<<1, 1024>>>();
    k_fill<<<(N_EDGES + 255) / 256, 256>>>(ei);
    k_gather<<<N_NODES / 8, 256>>>(x);
    k_prep_bt<<<dim3(HIDDEN / 32, IN_DIM / 32), 256>>>(W1);

    cudaFuncSetAttribute(k_gemm_mma, cudaFuncAttributeMaxDynamicSharedMemorySize, SMEM_TOTAL);
    k_gemm_mma<<<dim3(HIDDEN / 128, N_NODES / 128), 256, SMEM_TOTAL>>>(b1, W2);
    k_lsm<<<(N_NODES * N_CLASSES + 255) / 256, 256>>>(b2, out);
}

// round 7
// speedup vs baseline: 4.1235x; 1.0226x over previous
#include <cuda_runtime.h>
#include <cuda_fp16.h>
#include <cstdint>

#define N_NODES 8192
#define N_EDGES 65536
#define IN_DIM 768
#define HIDDEN 4096
#define N_CLASSES 16

// ---- scratch (device globals) ----
__device__ float g_dinv[N_NODES];
__device__ float g_logits[N_NODES * N_CLASSES];   // 512 KB
__device__ int   g_is64;
__device__ int   g_cnt[N_NODES];
__device__ int   g_off[N_NODES + 1];
__device__ int   g_cursor[N_NODES];
__device__ int   g_csr_src[N_EDGES];
// fp16 hi/lo splits
__device__ __half g_a_hi[N_NODES * IN_DIM];       // 12.6 MB
__device__ __half g_a_lo[N_NODES * IN_DIM];
__device__ __half g_bt_hi[HIDDEN * IN_DIM];       // 6.3 MB (W1^T)
__device__ __half g_bt_lo[HIDDEN * IN_DIM];

// ============================ PTX helpers (baseline ISA only) ============================
__device__ __forceinline__ uint32_t smem_to_u32(const void* p) {
    uint32_t a;
    asm("{ .reg .u64 t; cvta.to.shared.u64 t, %1; cvt.u32.u64 %0, t; }" : "=r"(a) : "l"(p));
    return a;
}
#define CP_ASYNC16(smem, gptr) \
    asm volatile("cp.async.cg.shared.global [%0], [%1], 16;" :: "r"(smem), "l"(gptr) : "memory")
#define CP_COMMIT() asm volatile("cp.async.commit_group;" ::: "memory")
#define CP_WAIT(n)  asm volatile("cp.async.wait_group %0;" :: "n"(n) : "memory")

__device__ __forceinline__ void ldsm4(uint32_t* r, uint32_t addr) {
    asm volatile("ldmatrix.sync.aligned.m8n8.x4.shared.b16 {%0,%1,%2,%3}, [%4];"
        : "=r"(r[0]), "=r"(r[1]), "=r"(r[2]), "=r"(r[3]) : "r"(addr));
}
__device__ __forceinline__ void mma16816(float* d, const uint32_t* a, const uint32_t* b) {
    asm volatile("mma.sync.aligned.m16n8k16.row.col.f32.f16.f16.f32 "
        "{%0,%1,%2,%3}, {%4,%5,%6,%7}, {%8,%9}, {%0,%1,%2,%3};"
        : "+f"(d[0]), "+f"(d[1]), "+f"(d[2]), "+f"(d[3])
        : "r"(a[0]), "r"(a[1]), "r"(a[2]), "r"(a[3]), "r"(b[0]), "r"(b[1]));
}

__device__ __forceinline__ int edge_at(const void* ei, int idx) {
    int v;
    if (g_is64) v = (int)((const long long*)ei)[idx];
    else        v = ((const int*)ei)[idx];
    return v & (N_NODES - 1);
}

// ============================ merged prep: W1 transpose/split + zero + detect ============================
// blocks [0,3072): prep_bt; [3072,3200): zero logits/cnt; block 3200: dtype detect
__global__ __launch_bounds__(256) void k_prep_all(const float* __restrict__ W1,
                                                  const int* __restrict__ ei32) {
    int b = blockIdx.x;
    if (b < 3072) {
        __shared__ float t[32][33];
        int bn = b & 127;
        int bk = b >> 7;
        int x = threadIdx.x & 31, y = threadIdx.x >> 5;
        #pragma unroll
        for (int r = 0; r < 4; r++) {
            int kl = y + r * 8;
            t[kl][x] = W1[(size_t)(bk * 32 + kl) * HIDDEN + bn * 32 + x];
        }
        __syncthreads();
        #pragma unroll
        for (int r = 0; r < 4; r++) {
            int nl = y + r * 8;
            float v = t[x][nl];
            __half h = __float2half(v);
            __half l = __float2half(v - __half2float(h));
            size_t o = (size_t)(bn * 32 + nl) * IN_DIM + bk * 32 + x;
            g_bt_hi[o] = h;
            g_bt_lo[o] = l;
        }
    } else if (b < 3200) {
        int i = (b - 3072) * 256 + threadIdx.x;
        if (i < N_NODES * N_CLASSES / 4)
            reinterpret_cast<float4*>(g_logits)[i] = make_float4(0.f, 0.f, 0.f, 0.f);
        if (i < N_NODES / 4)
            reinterpret_cast<int4*>(g_cnt)[i] = make_int4(0, 0, 0, 0);
    } else {
        __shared__ int s_any[256];
        int any = 0;
        #pragma unroll
        for (int r = 0; r < 4; r++) {
            int i = 1 + 2 * (threadIdx.x + 256 * r);
            any |= ei32[i];
        }
        s_any[threadIdx.x] = any;
        __syncthreads();
        for (int o = 128; o > 0; o >>= 1) {
            if (threadIdx.x < o) s_any[threadIdx.x] |= s_any[threadIdx.x + o];
            __syncthreads();
        }
        if (threadIdx.x == 0) g_is64 = (s_any[0] == 0) ? 1 : 0;
    }
}

__global__ void k_hist(const void* __restrict__ ei) {
    int e = blockIdx.x * blockDim.x + threadIdx.x;
    if (e < N_EDGES) atomicAdd(&g_cnt[edge_at(ei, N_EDGES + e)], 1);
}

// single block 1024 threads: shuffle-based scan -> offsets, cursor; dinv = rsqrt(cnt+1)
__global__ __launch_bounds__(1024) void k_scan() {
    const int t = threadIdx.x;
    const int lane = t & 31, warp = t >> 5;
    const int base = t * 8;
    int v[8];
    int s = 0;
    #pragma unroll
    for (int i = 0; i < 8; i++) { v[i] = g_cnt[base + i]; s += v[i]; }
    // inclusive warp scan of s
    int inc = s;
    #pragma unroll
    for (int o = 1; o < 32; o <<= 1) {
        int y = __shfl_up_sync(0xffffffffu, inc, o);
        if (lane >= o) inc += y;
    }
    __shared__ int wsum[32];
    if (lane == 31) wsum[warp] = inc;
    __syncthreads();
    if (warp == 0) {
        int ws = wsum[lane];
        int wi = ws;
        #pragma unroll
        for (int o = 1; o < 32; o <<= 1) {
            int y = __shfl_up_sync(0xffffffffu, wi, o);
            if (lane >= o) wi += y;
        }
        wsum[lane] = wi - ws;            // exclusive warp prefix
    }
    __syncthreads();
    int run = wsum[warp] + inc - s;      // exclusive prefix for this thread
    #pragma unroll
    for (int i = 0; i < 8; i++) {
        g_off[base + i] = run;
        g_cursor[base + i] = run;
        g_dinv[base + i] = rsqrtf((float)(v[i] + 1));
        run += v[i];
    }
    if (t == 1023) g_off[N_NODES] = run;
}

__global__ void k_fill(const void* __restrict__ ei) {
    int e = blockIdx.x * blockDim.x + threadIdx.x;
    if (e >= N_EDGES) return;
    int s = edge_at(ei, e);
    int d = edge_at(ei, N_EDGES + e);
    int pos = atomicAdd(&g_cursor[d], 1);
    g_csr_src[pos] = s;
}

// ---- gather aggregation (warp per node) + fp16 hi/lo split write ----
__global__ __launch_bounds__(256) void k_gather(const float* __restrict__ x) {
    int v = blockIdx.x * 8 + (threadIdx.x >> 5);
    int lane = threadIdx.x & 31;
    float dv = g_dinv[v];
    const float4* xv = reinterpret_cast<const float4*>(x + (size_t)v * IN_DIM);
    float4 acc[6];
    float sw = dv * dv;
    #pragma unroll
    for (int t = 0; t < 6; t++) {
        float4 a = xv[lane + 32 * t];
        acc[t].x = a.x * sw; acc[t].y = a.y * sw;
        acc[t].z = a.z * sw; acc[t].w = a.w * sw;
    }
    int e0 = g_off[v], e1 = g_off[v + 1];
    for (int p = e0; p < e1; p++) {
        int s = g_csr_src[p];
        float w = g_dinv[s] * dv;
        const float4* xs = reinterpret_cast<const float4*>(x + (size_t)s * IN_DIM);
        #pragma unroll
        for (int t = 0; t < 6; t++) {
            float4 a = xs[lane + 32 * t];
            acc[t].x += a.x * w; acc[t].y += a.y * w;
            acc[t].z += a.z * w; acc[t].w += a.w * w;
        }
    }
    #pragma unroll
    for (int t = 0; t < 6; t++) {
        int eb = v * IN_DIM + lane * 4 + 128 * t;
        float f[4] = {acc[t].x, acc[t].y, acc[t].z, acc[t].w};
        __half h[4], l[4];
        #pragma unroll
        for (int i = 0; i < 4; i++) {
            h[i] = __float2half(f[i]);
            l[i] = __float2half(f[i] - __half2float(h[i]));
        }
        __half2 h01 = __halves2half2(h[0], h[1]), h23 = __halves2half2(h[2], h[3]);
        __half2 l01 = __halves2half2(l[0], l[1]), l23 = __halves2half2(l[2], l[3]);
        uint2 hp = make_uint2(*(uint32_t*)&h01, *(uint32_t*)&h23);
        uint2 lp = make_uint2(*(uint32_t*)&l01, *(uint32_t*)&l23);
        *reinterpret_cast<uint2*>(g_a_hi + eb) = hp;
        *reinterpret_cast<uint2*>(g_a_lo + eb) = lp;
    }
}

// ============================ HMMA GEMM (shared-tile 3-term fp16) ============================
#define KCHUNK 24
#define STAGE_B 32768
#define H_STRIDE 130
#define W2S_OFF 98304
#define B1S_OFF (W2S_OFF + 8192)
#define SMEM_TOTAL (B1S_OFF + 512)

__global__ __launch_bounds__(256, 2) void k_gemm_mma(const float* __restrict__ b1,
                                                     const float* __restrict__ W2) {
    extern __shared__ __align__(128) char smem[];
    const uint32_t sb = smem_to_u32(smem);
    const int tid = threadIdx.x, lane = tid & 31, wid = tid >> 5;
    const int wm = wid & 1, wn = wid >> 1;
    const int bx = blockIdx.x, by = blockIdx.y;

    // stage W2 slice (128x16 f32) + b1 slice (128 f32)
    {
        const float4* s = reinterpret_cast<const float4*>(W2 + (size_t)bx * 128 * N_CLASSES);
        float4* d = reinterpret_cast<float4*>(smem + W2S_OFF);
        #pragma unroll
        for (int i = tid; i < 512; i += 256) d[i] = s[i];
        if (tid < 128) reinterpret_cast<float*>(smem + B1S_OFF)[tid] = b1[bx * 128 + tid];
    }

    float c[4][4][4];
    #pragma unroll
    for (int mi = 0; mi < 4; mi++)
        #pragma unroll
        for (int ni = 0; ni < 4; ni++)
            #pragma unroll
            for (int q = 0; q < 4; q++) c[mi][ni][q] = 0.0f;

    const int row_half = tid >> 2;       // 0..63
    const int chk = tid & 3;
    const int arow_g = by * 128;
    const int brow_g = bx * 128;

    auto load_stage = [&](int ch, int buf) {
        int kk = ch * 32;
        uint32_t sbase = sb + buf * STAGE_B;
        #pragma unroll
        for (int half = 0; half < 2; half++) {
            int row = row_half + half * 64;
            uint32_t soff = row * 64 + ((chk ^ (row & 3)) << 4);
            size_t goff = (size_t)row * IN_DIM + kk + chk * 8;
            CP_ASYNC16(sbase +     0 + soff, g_a_hi  + (size_t)arow_g * IN_DIM + goff);
            CP_ASYNC16(sbase +  8192 + soff, g_a_lo  + (size_t)arow_g * IN_DIM + goff);
            CP_ASYNC16(sbase + 16384 + soff, g_bt_hi + (size_t)brow_g * IN_DIM + goff);
            CP_ASYNC16(sbase + 24576 + soff, g_bt_lo + (size_t)brow_g * IN_DIM + goff);
        }
        CP_COMMIT();
    };

    load_stage(0, 0);
    load_stage(1, 1);

    #pragma unroll 3
    for (int ch = 0; ch < KCHUNK; ch++) {
        if (ch + 2 < KCHUNK) { CP_WAIT(1); } else { CP_WAIT(0); }
        __syncthreads();
        if (ch + 2 < KCHUNK) load_stage(ch + 2, (ch + 2) % 3);

        uint32_t aHB = sb + (ch % 3) * STAGE_B;
        uint32_t aLB = aHB + 8192;
        uint32_t bHB = aHB + 16384;
        uint32_t bLB = aHB + 24576;

        #pragma unroll
        for (int kk = 0; kk < 2; kk++) {
            uint32_t a[4][4], bh[4][2], bl[4][2];
            int arow = wm * 64 + (lane & 15);
            int akc = kk * 2 + (lane >> 4);
            #pragma unroll
            for (int mi = 0; mi < 4; mi++) {
                int row = arow + mi * 16;
                ldsm4(a[mi], aHB + row * 64 + ((akc ^ (row & 3)) << 4));
            }
            int bnl = (lane & 7) + ((lane >> 4) << 3);
            int bkc = kk * 2 + ((lane >> 3) & 1);
            #pragma unroll
            for (int nn = 0; nn < 2; nn++) {
                int n = wn * 32 + nn * 16 + bnl;
                uint32_t soff = n * 64 + ((bkc ^ (n & 3)) << 4);
                uint32_t t[4];
                ldsm4(t, bHB + soff);
                bh[nn * 2][0] = t[0]; bh[nn * 2][1] = t[1];
                bh[nn * 2 + 1][0] = t[2]; bh[nn * 2 + 1][1] = t[3];
                ldsm4(t, bLB + soff);
                bl[nn * 2][0] = t[0]; bl[nn * 2][1] = t[1];
                bl[nn * 2 + 1][0] = t[2]; bl[nn * 2 + 1][1] = t[3];
            }
            #pragma unroll
            for (int mi = 0; mi < 4; mi++)
                #pragma unroll
                for (int ni = 0; ni < 4; ni++) {
                    mma16816(c[mi][ni], a[mi], bh[ni]);
                    mma16816(c[mi][ni], a[mi], bl[ni]);
                }
            #pragma unroll
            for (int mi = 0; mi < 4; mi++) {
                int row = arow + mi * 16;
                ldsm4(a[mi], aLB + row * 64 + ((akc ^ (row & 3)) << 4));
            }
            #pragma unroll
            for (int mi = 0; mi < 4; mi++)
                #pragma unroll
                for (int ni = 0; ni < 4; ni++)
                    mma16816(c[mi][ni], a[mi], bh[ni]);
        }
    }

    // epilogue: stage h to smem, then h @ W2 slice -> atomic logits
    __syncthreads();
    float* h = reinterpret_cast<float*>(smem);
    const float* b1s = reinterpret_cast<const float*>(smem + B1S_OFF);
    #pragma unroll
    for (int mi = 0; mi < 4; mi++) {
        int r0 = wm * 64 + mi * 16 + (lane >> 2);
        #pragma unroll
        for (int ni = 0; ni < 4; ni++) {
            int n = wn * 32 + ni * 8 + (lane & 3) * 2;
            *reinterpret_cast<float2*>(&h[r0 * H_STRIDE + n]) =
                make_float2(c[mi][ni][0], c[mi][ni][1]);
            *reinterpret_cast<float2*>(&h[(r0 + 8) * H_STRIDE + n]) =
                make_float2(c[mi][ni][2], c[mi][ni][3]);
        }
    }
    __syncthreads();
    {
        int r = tid >> 1;
        int cg = (tid & 1) * 8;
        const float* w2s = reinterpret_cast<const float*>(smem + W2S_OFF);
        float acc[8];
        #pragma unroll
        for (int q = 0; q < 8; q++) acc[q] = 0.0f;
        #pragma unroll 4
        for (int n = 0; n < 128; n++) {
            float hv = fmaxf(h[r * H_STRIDE + n] + b1s[n], 0.0f);
            const float4* w = reinterpret_cast<const float4*>(w2s + n * N_CLASSES + cg);
            float4 w0 = w[0], w1 = w[1];
            acc[0] += hv * w0.x; acc[1] += hv * w0.y;
            acc[2] += hv * w0.z; acc[3] += hv * w0.w;
            acc[4] += hv * w1.x; acc[5] += hv * w1.y;
            acc[6] += hv * w1.z; acc[7] += hv * w1.w;
        }
        float* lg = &g_logits[(by * 128 + r) * N_CLASSES + cg];
        #pragma unroll
        for (int q = 0; q < 8; q++) atomicAdd(&lg[q], acc[q]);
    }
}

// ---- log_softmax over 16 classes ----
__global__ void k_lsm(const float* __restrict__ b2, float* __restrict__ out) {
    int t = blockIdx.x * blockDim.x + threadIdx.x;
    if (t >= N_NODES * N_CLASSES) return;
    int c = t & 15;
    float v = g_logits[t] + b2[c];
    float m = v;
    #pragma unroll
    for (int k = 8; k > 0; k >>= 1)
        m = fmaxf(m, __shfl_xor_sync(0xffffffffu, m, k, 16));
    float s = __expf(v - m);
    #pragma unroll
    for (int k = 8; k > 0; k >>= 1)
        s += __shfl_xor_sync(0xffffffffu, s, k, 16);
    out[t] = v - m - __logf(s);
}

// ---- eager module load ----
namespace {
struct EagerLoad {
    EagerLoad() {
        void* p = nullptr;
        cudaGetSymbolAddress(&p, g_logits);
        cudaGetSymbolAddress(&p, g_dinv);
        cudaGetSymbolAddress(&p, g_is64);
        cudaGetSymbolAddress(&p, g_cnt);
        cudaGetSymbolAddress(&p, g_off);
        cudaGetSymbolAddress(&p, g_cursor);
        cudaGetSymbolAddress(&p, g_csr_src);
        cudaGetSymbolAddress(&p, g_a_hi);
        cudaGetSymbolAddress(&p, g_a_lo);
        cudaGetSymbolAddress(&p, g_bt_hi);
        cudaGetSymbolAddress(&p, g_bt_lo);
        cudaFuncAttributes a;
        cudaFuncGetAttributes(&a, k_prep_all);
        cudaFuncGetAttributes(&a, k_hist);
        cudaFuncGetAttributes(&a, k_scan);
        cudaFuncGetAttributes(&a, k_fill);
        cudaFuncGetAttributes(&a, k_gather);
        cudaFuncGetAttributes(&a, k_gemm_mma);
        cudaFuncGetAttributes(&a, k_lsm);
        cudaFuncSetAttribute(k_gemm_mma, cudaFuncAttributeMaxDynamicSharedMemorySize, SMEM_TOTAL);
    }
};
EagerLoad g_eager_load;
}

extern "C" void kernel_launch(void* const* d_in, const int* in_sizes, int n_in,
                              void* d_out, int out_size) {
    const float* x  = (const float*)d_in[0];
    const void*  ei = d_in[1];                 // [2, E], int32 OR int64 (detected)
    const float* W1 = (const float*)d_in[2];
    const float* b1 = (const float*)d_in[3];
    const float* W2 = (const float*)d_in[4];
    const float* b2 = (const float*)d_in[5];
    float* out = (float*)d_out;

    k_prep_all<<<3201, 256>>>(W1, (const int*)ei);
    k_hist<<<(N_EDGES + 255) / 256, 256>>>(ei);
    k_scan<<<1, 1024>>>();
    k_fill<<<(N_EDGES + 255) / 256, 256>>>(ei);
    k_gather<<<N_NODES / 8, 256>>>(x);

    cudaFuncSetAttribute(k_gemm_mma, cudaFuncAttributeMaxDynamicSharedMemorySize, SMEM_TOTAL);
    k_gemm_mma<<<dim3(HIDDEN / 128, N_NODES / 128), 256, SMEM_TOTAL>>>(b1, W2);
    k_lsm<<<(N_NODES * N_CLASSES + 255) / 256, 256>>>(b2, out);
}

// round 8
// speedup vs baseline: 4.9873x; 1.2095x over previous
#include <cuda_runtime.h>
#include <cuda_fp16.h>
#include <cstdint>

#define N_NODES 8192
#define N_EDGES 65536
#define IN_DIM 768
#define HIDDEN 4096
#define N_CLASSES 16

// ---- scratch (device globals) ----
__device__ float g_dinv[N_NODES];
__device__ float g_logits[N_NODES * N_CLASSES];   // 512 KB
__device__ int   g_is64;
__device__ int   g_cnt[N_NODES];
__device__ int   g_off[N_NODES + 1];
__device__ int   g_cursor[N_NODES];
__device__ int   g_csr_src[N_EDGES];
// fp16 splits: A 2-term (hi+lo, exact to 2^-22), B single fp16 (error ~2^-12)
__device__ __half g_a_hi[N_NODES * IN_DIM];       // 12.6 MB
__device__ __half g_a_lo[N_NODES * IN_DIM];
__device__ __half g_bt_hi[HIDDEN * IN_DIM];       // 6.3 MB (W1^T)

// ============================ PTX helpers (baseline ISA only) ============================
__device__ __forceinline__ uint32_t smem_to_u32(const void* p) {
    uint32_t a;
    asm("{ .reg .u64 t; cvta.to.shared.u64 t, %1; cvt.u32.u64 %0, t; }" : "=r"(a) : "l"(p));
    return a;
}
#define CP_ASYNC16(smem, gptr) \
    asm volatile("cp.async.cg.shared.global [%0], [%1], 16;" :: "r"(smem), "l"(gptr) : "memory")
#define CP_COMMIT() asm volatile("cp.async.commit_group;" ::: "memory")
#define CP_WAIT(n)  asm volatile("cp.async.wait_group %0;" :: "n"(n) : "memory")

__device__ __forceinline__ void ldsm4(uint32_t* r, uint32_t addr) {
    asm volatile("ldmatrix.sync.aligned.m8n8.x4.shared.b16 {%0,%1,%2,%3}, [%4];"
        : "=r"(r[0]), "=r"(r[1]), "=r"(r[2]), "=r"(r[3]) : "r"(addr));
}
__device__ __forceinline__ void mma16816(float* d, const uint32_t* a, const uint32_t* b) {
    asm volatile("mma.sync.aligned.m16n8k16.row.col.f32.f16.f16.f32 "
        "{%0,%1,%2,%3}, {%4,%5,%6,%7}, {%8,%9}, {%0,%1,%2,%3};"
        : "+f"(d[0]), "+f"(d[1]), "+f"(d[2]), "+f"(d[3])
        : "r"(a[0]), "r"(a[1]), "r"(a[2]), "r"(a[3]), "r"(b[0]), "r"(b[1]));
}

__device__ __forceinline__ int edge_at(const void* ei, int idx) {
    int v;
    if (g_is64) v = (int)((const long long*)ei)[idx];
    else        v = ((const int*)ei)[idx];
    return v & (N_NODES - 1);
}

// ============================ merged prep: W1 transpose/split + zero + detect ============================
// blocks [0,3072): prep_bt; [3072,3200): zero logits/cnt; block 3200: dtype detect
__global__ __launch_bounds__(256) void k_prep_all(const float* __restrict__ W1,
                                                  const int* __restrict__ ei32) {
    int b = blockIdx.x;
    if (b < 3072) {
        __shared__ float t[32][33];
        int bn = b & 127;
        int bk = b >> 7;
        int x = threadIdx.x & 31, y = threadIdx.x >> 5;
        #pragma unroll
        for (int r = 0; r < 4; r++) {
            int kl = y + r * 8;
            t[kl][x] = W1[(size_t)(bk * 32 + kl) * HIDDEN + bn * 32 + x];
        }
        __syncthreads();
        #pragma unroll
        for (int r = 0; r < 4; r++) {
            int nl = y + r * 8;
            float v = t[x][nl];
            size_t o = (size_t)(bn * 32 + nl) * IN_DIM + bk * 32 + x;
            g_bt_hi[o] = __float2half(v);
        }
    } else if (b < 3200) {
        int i = (b - 3072) * 256 + threadIdx.x;
        if (i < N_NODES * N_CLASSES / 4)
            reinterpret_cast<float4*>(g_logits)[i] = make_float4(0.f, 0.f, 0.f, 0.f);
        if (i < N_NODES / 4)
            reinterpret_cast<int4*>(g_cnt)[i] = make_int4(0, 0, 0, 0);
    } else {
        __shared__ int s_any[256];
        int any = 0;
        #pragma unroll
        for (int r = 0; r < 4; r++) {
            int i = 1 + 2 * (threadIdx.x + 256 * r);
            any |= ei32[i];
        }
        s_any[threadIdx.x] = any;
        __syncthreads();
        for (int o = 128; o > 0; o >>= 1) {
            if (threadIdx.x < o) s_any[threadIdx.x] |= s_any[threadIdx.x + o];
            __syncthreads();
        }
        if (threadIdx.x == 0) g_is64 = (s_any[0] == 0) ? 1 : 0;
    }
}

__global__ void k_hist(const void* __restrict__ ei) {
    int e = blockIdx.x * blockDim.x + threadIdx.x;
    if (e < N_EDGES) atomicAdd(&g_cnt[edge_at(ei, N_EDGES + e)], 1);
}

// single block 1024 threads: shuffle-based scan -> offsets, cursor; dinv = rsqrt(cnt+1)
__global__ __launch_bounds__(1024) void k_scan() {
    const int t = threadIdx.x;
    const int lane = t & 31, warp = t >> 5;
    const int base = t * 8;
    int v[8];
    int s = 0;
    #pragma unroll
    for (int i = 0; i < 8; i++) { v[i] = g_cnt[base + i]; s += v[i]; }
    int inc = s;
    #pragma unroll
    for (int o = 1; o < 32; o <<= 1) {
        int y = __shfl_up_sync(0xffffffffu, inc, o);
        if (lane >= o) inc += y;
    }
    __shared__ int wsum[32];
    if (lane == 31) wsum[warp] = inc;
    __syncthreads();
    if (warp == 0) {
        int ws = wsum[lane];
        int wi = ws;
        #pragma unroll
        for (int o = 1; o < 32; o <<= 1) {
            int y = __shfl_up_sync(0xffffffffu, wi, o);
            if (lane >= o) wi += y;
        }
        wsum[lane] = wi - ws;
    }
    __syncthreads();
    int run = wsum[warp] + inc - s;
    #pragma unroll
    for (int i = 0; i < 8; i++) {
        g_off[base + i] = run;
        g_cursor[base + i] = run;
        g_dinv[base + i] = rsqrtf((float)(v[i] + 1));
        run += v[i];
    }
    if (t == 1023) g_off[N_NODES] = run;
}

__global__ void k_fill(const void* __restrict__ ei) {
    int e = blockIdx.x * blockDim.x + threadIdx.x;
    if (e >= N_EDGES) return;
    int s = edge_at(ei, e);
    int d = edge_at(ei, N_EDGES + e);
    int pos = atomicAdd(&g_cursor[d], 1);
    g_csr_src[pos] = s;
}

// ---- gather aggregation (warp per node) + fp16 hi/lo split write ----
__global__ __launch_bounds__(256) void k_gather(const float* __restrict__ x) {
    int v = blockIdx.x * 8 + (threadIdx.x >> 5);
    int lane = threadIdx.x & 31;
    float dv = g_dinv[v];
    const float4* xv = reinterpret_cast<const float4*>(x + (size_t)v * IN_DIM);
    float4 acc[6];
    float sw = dv * dv;
    #pragma unroll
    for (int t = 0; t < 6; t++) {
        float4 a = xv[lane + 32 * t];
        acc[t].x = a.x * sw; acc[t].y = a.y * sw;
        acc[t].z = a.z * sw; acc[t].w = a.w * sw;
    }
    int e0 = g_off[v], e1 = g_off[v + 1];
    for (int p = e0; p < e1; p++) {
        int s = g_csr_src[p];
        float w = g_dinv[s] * dv;
        const float4* xs = reinterpret_cast<const float4*>(x + (size_t)s * IN_DIM);
        #pragma unroll
        for (int t = 0; t < 6; t++) {
            float4 a = xs[lane + 32 * t];
            acc[t].x += a.x * w; acc[t].y += a.y * w;
            acc[t].z += a.z * w; acc[t].w += a.w * w;
        }
    }
    #pragma unroll
    for (int t = 0; t < 6; t++) {
        int eb = v * IN_DIM + lane * 4 + 128 * t;
        float f[4] = {acc[t].x, acc[t].y, acc[t].z, acc[t].w};
        __half h[4], l[4];
        #pragma unroll
        for (int i = 0; i < 4; i++) {
            h[i] = __float2half(f[i]);
            l[i] = __float2half(f[i] - __half2float(h[i]));
        }
        __half2 h01 = __halves2half2(h[0], h[1]), h23 = __halves2half2(h[2], h[3]);
        __half2 l01 = __halves2half2(l[0], l[1]), l23 = __halves2half2(l[2], l[3]);
        uint2 hp = make_uint2(*(uint32_t*)&h01, *(uint32_t*)&h23);
        uint2 lp = make_uint2(*(uint32_t*)&l01, *(uint32_t*)&l23);
        *reinterpret_cast<uint2*>(g_a_hi + eb) = hp;
        *reinterpret_cast<uint2*>(g_a_lo + eb) = lp;
    }
}

// ============================ HMMA GEMM (2-term fp16: AhBh + AlBh) ============================
// Per 32-wide k-chunk, stage {Ah, Al, Bh} (24KB); 3-stage cp.async pipeline.
// Block tile 128x128, 8 warps (2M x 4N), warp tile 64x32.
#define KCHUNK 24
#define STAGE_B 24576
#define H_STRIDE 130
#define W2S_OFF 73728
#define B1S_OFF (W2S_OFF + 8192)
#define SMEM_TOTAL (B1S_OFF + 512)

__global__ __launch_bounds__(256, 2) void k_gemm_mma(const float* __restrict__ b1,
                                                     const float* __restrict__ W2) {
    extern __shared__ __align__(128) char smem[];
    const uint32_t sb = smem_to_u32(smem);
    const int tid = threadIdx.x, lane = tid & 31, wid = tid >> 5;
    const int wm = wid & 1, wn = wid >> 1;
    const int bx = blockIdx.x, by = blockIdx.y;

    // stage W2 slice (128x16 f32) + b1 slice (128 f32)
    {
        const float4* s = reinterpret_cast<const float4*>(W2 + (size_t)bx * 128 * N_CLASSES);
        float4* d = reinterpret_cast<float4*>(smem + W2S_OFF);
        #pragma unroll
        for (int i = tid; i < 512; i += 256) d[i] = s[i];
        if (tid < 128) reinterpret_cast<float*>(smem + B1S_OFF)[tid] = b1[bx * 128 + tid];
    }

    float c[4][4][4];
    #pragma unroll
    for (int mi = 0; mi < 4; mi++)
        #pragma unroll
        for (int ni = 0; ni < 4; ni++)
            #pragma unroll
            for (int q = 0; q < 4; q++) c[mi][ni][q] = 0.0f;

    const int row_half = tid >> 2;       // 0..63
    const int chk = tid & 3;
    const int arow_g = by * 128;
    const int brow_g = bx * 128;

    auto load_stage = [&](int ch, int buf) {
        int kk = ch * 32;
        uint32_t sbase = sb + buf * STAGE_B;
        #pragma unroll
        for (int half = 0; half < 2; half++) {
            int row = row_half + half * 64;
            uint32_t soff = row * 64 + ((chk ^ (row & 3)) << 4);
            size_t goff = (size_t)row * IN_DIM + kk + chk * 8;
            CP_ASYNC16(sbase +     0 + soff, g_a_hi  + (size_t)arow_g * IN_DIM + goff);
            CP_ASYNC16(sbase +  8192 + soff, g_a_lo  + (size_t)arow_g * IN_DIM + goff);
            CP_ASYNC16(sbase + 16384 + soff, g_bt_hi + (size_t)brow_g * IN_DIM + goff);
        }
        CP_COMMIT();
    };

    load_stage(0, 0);
    load_stage(1, 1);

    #pragma unroll 3
    for (int ch = 0; ch < KCHUNK; ch++) {
        if (ch + 2 < KCHUNK) { CP_WAIT(1); } else { CP_WAIT(0); }
        __syncthreads();
        if (ch + 2 < KCHUNK) load_stage(ch + 2, (ch + 2) % 3);

        uint32_t aHB = sb + (ch % 3) * STAGE_B;
        uint32_t aLB = aHB + 8192;
        uint32_t bHB = aHB + 16384;

        #pragma unroll
        for (int kk = 0; kk < 2; kk++) {
            uint32_t a[4][4], al[4][4], bh[4][2];
            int arow = wm * 64 + (lane & 15);
            int akc = kk * 2 + (lane >> 4);
            #pragma unroll
            for (int mi = 0; mi < 4; mi++) {
                int row = arow + mi * 16;
                uint32_t soff = row * 64 + ((akc ^ (row & 3)) << 4);
                ldsm4(a[mi], aHB + soff);
                ldsm4(al[mi], aLB + soff);
            }
            int bnl = (lane & 7) + ((lane >> 4) << 3);
            int bkc = kk * 2 + ((lane >> 3) & 1);
            #pragma unroll
            for (int nn = 0; nn < 2; nn++) {
                int n = wn * 32 + nn * 16 + bnl;
                uint32_t t[4];
                ldsm4(t, bHB + n * 64 + ((bkc ^ (n & 3)) << 4));
                bh[nn * 2][0] = t[0]; bh[nn * 2][1] = t[1];
                bh[nn * 2 + 1][0] = t[2]; bh[nn * 2 + 1][1] = t[3];
            }
            #pragma unroll
            for (int mi = 0; mi < 4; mi++)
                #pragma unroll
                for (int ni = 0; ni < 4; ni++) {
                    mma16816(c[mi][ni], a[mi], bh[ni]);
                    mma16816(c[mi][ni], al[mi], bh[ni]);
                }
        }
    }

    // epilogue: stage h to smem, then h @ W2 slice -> atomic logits
    __syncthreads();
    float* h = reinterpret_cast<float*>(smem);
    const float* b1s = reinterpret_cast<const float*>(smem + B1S_OFF);
    #pragma unroll
    for (int mi = 0; mi < 4; mi++) {
        int r0 = wm * 64 + mi * 16 + (lane >> 2);
        #pragma unroll
        for (int ni = 0; ni < 4; ni++) {
            int n = wn * 32 + ni * 8 + (lane & 3) * 2;
            *reinterpret_cast<float2*>(&h[r0 * H_STRIDE + n]) =
                make_float2(c[mi][ni][0], c[mi][ni][1]);
            *reinterpret_cast<float2*>(&h[(r0 + 8) * H_STRIDE + n]) =
                make_float2(c[mi][ni][2], c[mi][ni][3]);
        }
    }
    __syncthreads();
    {
        int r = tid >> 1;
        int cg = (tid & 1) * 8;
        const float* w2s = reinterpret_cast<const float*>(smem + W2S_OFF);
        float acc[8];
        #pragma unroll
        for (int q = 0; q < 8; q++) acc[q] = 0.0f;
        #pragma unroll 4
        for (int n = 0; n < 128; n++) {
            float hv = fmaxf(h[r * H_STRIDE + n] + b1s[n], 0.0f);
            const float4* w = reinterpret_cast<const float4*>(w2s + n * N_CLASSES + cg);
            float4 w0 = w[0], w1 = w[1];
            acc[0] += hv * w0.x; acc[1] += hv * w0.y;
            acc[2] += hv * w0.z; acc[3] += hv * w0.w;
            acc[4] += hv * w1.x; acc[5] += hv * w1.y;
            acc[6] += hv * w1.z; acc[7] += hv * w1.w;
        }
        float* lg = &g_logits[(by * 128 + r) * N_CLASSES + cg];
        #pragma unroll
        for (int q = 0; q < 8; q++) atomicAdd(&lg[q], acc[q]);
    }
}

// ---- log_softmax over 16 classes ----
__global__ void k_lsm(const float* __restrict__ b2, float* __restrict__ out) {
    int t = blockIdx.x * blockDim.x + threadIdx.x;
    if (t >= N_NODES * N_CLASSES) return;
    int c = t & 15;
    float v = g_logits[t] + b2[c];
    float m = v;
    #pragma unroll
    for (int k = 8; k > 0; k >>= 1)
        m = fmaxf(m, __shfl_xor_sync(0xffffffffu, m, k, 16));
    float s = __expf(v - m);
    #pragma unroll
    for (int k = 8; k > 0; k >>= 1)
        s += __shfl_xor_sync(0xffffffffu, s, k, 16);
    out[t] = v - m - __logf(s);
}

// ---- eager module load ----
namespace {
struct EagerLoad {
    EagerLoad() {
        void* p = nullptr;
        cudaGetSymbolAddress(&p, g_logits);
        cudaGetSymbolAddress(&p, g_dinv);
        cudaGetSymbolAddress(&p, g_is64);
        cudaGetSymbolAddress(&p, g_cnt);
        cudaGetSymbolAddress(&p, g_off);
        cudaGetSymbolAddress(&p, g_cursor);
        cudaGetSymbolAddress(&p, g_csr_src);
        cudaGetSymbolAddress(&p, g_a_hi);
        cudaGetSymbolAddress(&p, g_a_lo);
        cudaGetSymbolAddress(&p, g_bt_hi);
        cudaFuncAttributes a;
        cudaFuncGetAttributes(&a, k_prep_all);
        cudaFuncGetAttributes(&a, k_hist);
        cudaFuncGetAttributes(&a, k_scan);
        cudaFuncGetAttributes(&a, k_fill);
        cudaFuncGetAttributes(&a, k_gather);
        cudaFuncGetAttributes(&a, k_gemm_mma);
        cudaFuncGetAttributes(&a, k_lsm);
        cudaFuncSetAttribute(k_gemm_mma, cudaFuncAttributeMaxDynamicSharedMemorySize, SMEM_TOTAL);
    }
};
EagerLoad g_eager_load;
}

extern "C" void kernel_launch(void* const* d_in, const int* in_sizes, int n_in,
                              void* d_out, int out_size) {
    const float* x  = (const float*)d_in[0];
    const void*  ei = d_in[1];                 // [2, E], int32 OR int64 (detected)
    const float* W1 = (const float*)d_in[2];
    const float* b1 = (const float*)d_in[3];
    const float* W2 = (const float*)d_in[4];
    const float* b2 = (const float*)d_in[5];
    float* out = (float*)d_out;

    k_prep_all<<<3201, 256>>>(W1, (const int*)ei);
    k_hist<<<(N_EDGES + 255) / 256, 256>>>(ei);
    k_scan<<<1, 1024>>>();
    k_fill<<<(N_EDGES + 255) / 256, 256>>>(ei);
    k_gather<<<N_NODES / 8, 256>>>(x);

    cudaFuncSetAttribute(k_gemm_mma, cudaFuncAttributeMaxDynamicSharedMemorySize, SMEM_TOTAL);
    k_gemm_mma<<<dim3(HIDDEN / 128, N_NODES / 128), 256, SMEM_TOTAL>>>(b1, W2);
    k_lsm<<<(N_NODES * N_CLASSES + 255) / 256, 256>>>(b2, out);
}

// round 9
// speedup vs baseline: 6.7722x; 1.3579x over previous
#include <cuda_runtime.h>
#include <cuda_fp16.h>
#include <cstdint>

#define N_NODES 8192
#define N_EDGES 65536
#define IN_DIM 768
#define HIDDEN 4096
#define N_CLASSES 16

// ---- scratch (device globals) ----
__device__ float g_dinv[N_NODES];
__device__ float g_logits[N_NODES * N_CLASSES];   // 512 KB
__device__ int   g_is64;
__device__ int   g_cnt[N_NODES];
__device__ int   g_off[N_NODES + 1];
__device__ int   g_cursor[N_NODES];
__device__ int   g_csr_src[N_EDGES];
// fp16 operands (single term; error ~2^-12 relative, averages to ~2.6e-5 on output)
__device__ __half g_a_hi[N_NODES * IN_DIM];       // 12.6 MB
__device__ __half g_bt_hi[HIDDEN * IN_DIM];       // 6.3 MB (W1^T)

// ============================ PTX helpers (baseline ISA only) ============================
__device__ __forceinline__ uint32_t smem_to_u32(const void* p) {
    uint32_t a;
    asm("{ .reg .u64 t; cvta.to.shared.u64 t, %1; cvt.u32.u64 %0, t; }" : "=r"(a) : "l"(p));
    return a;
}
#define CP_ASYNC16(smem, gptr) \
    asm volatile("cp.async.cg.shared.global [%0], [%1], 16;" :: "r"(smem), "l"(gptr) : "memory")
#define CP_COMMIT() asm volatile("cp.async.commit_group;" ::: "memory")
#define CP_WAIT(n)  asm volatile("cp.async.wait_group %0;" :: "n"(n) : "memory")

__device__ __forceinline__ void ldsm4(uint32_t* r, uint32_t addr) {
    asm volatile("ldmatrix.sync.aligned.m8n8.x4.shared.b16 {%0,%1,%2,%3}, [%4];"
        : "=r"(r[0]), "=r"(r[1]), "=r"(r[2]), "=r"(r[3]) : "r"(addr));
}
__device__ __forceinline__ void mma16816(float* d, const uint32_t* a, const uint32_t* b) {
    asm volatile("mma.sync.aligned.m16n8k16.row.col.f32.f16.f16.f32 "
        "{%0,%1,%2,%3}, {%4,%5,%6,%7}, {%8,%9}, {%0,%1,%2,%3};"
        : "+f"(d[0]), "+f"(d[1]), "+f"(d[2]), "+f"(d[3])
        : "r"(a[0]), "r"(a[1]), "r"(a[2]), "r"(a[3]), "r"(b[0]), "r"(b[1]));
}

__device__ __forceinline__ int edge_at(const void* ei, int idx) {
    int v;
    if (g_is64) v = (int)((const long long*)ei)[idx];
    else        v = ((const int*)ei)[idx];
    return v & (N_NODES - 1);
}

// ============================ merged prep: W1 transpose + zero + detect ============================
// blocks [0,3072): prep_bt; [3072,3200): zero logits/cnt; block 3200: dtype detect
__global__ __launch_bounds__(256) void k_prep_all(const float* __restrict__ W1,
                                                  const int* __restrict__ ei32) {
    int b = blockIdx.x;
    if (b < 3072) {
        __shared__ float t[32][33];
        int bn = b & 127;
        int bk = b >> 7;
        int x = threadIdx.x & 31, y = threadIdx.x >> 5;
        #pragma unroll
        for (int r = 0; r < 4; r++) {
            int kl = y + r * 8;
            t[kl][x] = W1[(size_t)(bk * 32 + kl) * HIDDEN + bn * 32 + x];
        }
        __syncthreads();
        #pragma unroll
        for (int r = 0; r < 4; r++) {
            int nl = y + r * 8;
            float v = t[x][nl];
            size_t o = (size_t)(bn * 32 + nl) * IN_DIM + bk * 32 + x;
            g_bt_hi[o] = __float2half(v);
        }
    } else if (b < 3200) {
        int i = (b - 3072) * 256 + threadIdx.x;
        if (i < N_NODES * N_CLASSES / 4)
            reinterpret_cast<float4*>(g_logits)[i] = make_float4(0.f, 0.f, 0.f, 0.f);
        if (i < N_NODES / 4)
            reinterpret_cast<int4*>(g_cnt)[i] = make_int4(0, 0, 0, 0);
    } else {
        __shared__ int s_any[256];
        int any = 0;
        #pragma unroll
        for (int r = 0; r < 4; r++) {
            int i = 1 + 2 * (threadIdx.x + 256 * r);
            any |= ei32[i];
        }
        s_any[threadIdx.x] = any;
        __syncthreads();
        for (int o = 128; o > 0; o >>= 1) {
            if (threadIdx.x < o) s_any[threadIdx.x] |= s_any[threadIdx.x + o];
            __syncthreads();
        }
        if (threadIdx.x == 0) g_is64 = (s_any[0] == 0) ? 1 : 0;
    }
}

__global__ void k_hist(const void* __restrict__ ei) {
    int e = blockIdx.x * blockDim.x + threadIdx.x;
    if (e < N_EDGES) atomicAdd(&g_cnt[edge_at(ei, N_EDGES + e)], 1);
}

// single block 1024 threads: shuffle-based scan -> offsets, cursor; dinv = rsqrt(cnt+1)
__global__ __launch_bounds__(1024) void k_scan() {
    const int t = threadIdx.x;
    const int lane = t & 31, warp = t >> 5;
    const int base = t * 8;
    int v[8];
    int s = 0;
    #pragma unroll
    for (int i = 0; i < 8; i++) { v[i] = g_cnt[base + i]; s += v[i]; }
    int inc = s;
    #pragma unroll
    for (int o = 1; o < 32; o <<= 1) {
        int y = __shfl_up_sync(0xffffffffu, inc, o);
        if (lane >= o) inc += y;
    }
    __shared__ int wsum[32];
    if (lane == 31) wsum[warp] = inc;
    __syncthreads();
    if (warp == 0) {
        int ws = wsum[lane];
        int wi = ws;
        #pragma unroll
        for (int o = 1; o < 32; o <<= 1) {
            int y = __shfl_up_sync(0xffffffffu, wi, o);
            if (lane >= o) wi += y;
        }
        wsum[lane] = wi - ws;
    }
    __syncthreads();
    int run = wsum[warp] + inc - s;
    #pragma unroll
    for (int i = 0; i < 8; i++) {
        g_off[base + i] = run;
        g_cursor[base + i] = run;
        g_dinv[base + i] = rsqrtf((float)(v[i] + 1));
        run += v[i];
    }
    if (t == 1023) g_off[N_NODES] = run;
}

__global__ void k_fill(const void* __restrict__ ei) {
    int e = blockIdx.x * blockDim.x + threadIdx.x;
    if (e >= N_EDGES) return;
    int s = edge_at(ei, e);
    int d = edge_at(ei, N_EDGES + e);
    int pos = atomicAdd(&g_cursor[d], 1);
    g_csr_src[pos] = s;
}

// ---- gather aggregation (warp per node) + fp16 write ----
__global__ __launch_bounds__(256) void k_gather(const float* __restrict__ x) {
    int v = blockIdx.x * 8 + (threadIdx.x >> 5);
    int lane = threadIdx.x & 31;
    float dv = g_dinv[v];
    const float4* xv = reinterpret_cast<const float4*>(x + (size_t)v * IN_DIM);
    float4 acc[6];
    float sw = dv * dv;
    #pragma unroll
    for (int t = 0; t < 6; t++) {
        float4 a = xv[lane + 32 * t];
        acc[t].x = a.x * sw; acc[t].y = a.y * sw;
        acc[t].z = a.z * sw; acc[t].w = a.w * sw;
    }
    int e0 = g_off[v], e1 = g_off[v + 1];
    for (int p = e0; p < e1; p++) {
        int s = g_csr_src[p];
        float w = g_dinv[s] * dv;
        const float4* xs = reinterpret_cast<const float4*>(x + (size_t)s * IN_DIM);
        #pragma unroll
        for (int t = 0; t < 6; t++) {
            float4 a = xs[lane + 32 * t];
            acc[t].x += a.x * w; acc[t].y += a.y * w;
            acc[t].z += a.z * w; acc[t].w += a.w * w;
        }
    }
    #pragma unroll
    for (int t = 0; t < 6; t++) {
        int eb = v * IN_DIM + lane * 4 + 128 * t;
        __half2 h01 = __halves2half2(__float2half(acc[t].x), __float2half(acc[t].y));
        __half2 h23 = __halves2half2(__float2half(acc[t].z), __float2half(acc[t].w));
        *reinterpret_cast<uint2*>(g_a_hi + eb) =
            make_uint2(*(uint32_t*)&h01, *(uint32_t*)&h23);
    }
}

// ============================ HMMA GEMM (single-term fp16) ============================
// Per 32-wide k-chunk, stage {Ah, Bh} (16KB); 3-stage cp.async pipeline.
// Block tile 128x128, 8 warps (2M x 4N), warp tile 64x32.
#define KCHUNK 24
#define STAGE_B 16384
#define H_STRIDE 130
#define W2S_OFF 66560
#define B1S_OFF (W2S_OFF + 8192)
#define SMEM_TOTAL (B1S_OFF + 512)

__global__ __launch_bounds__(256, 2) void k_gemm_mma(const float* __restrict__ b1,
                                                     const float* __restrict__ W2) {
    extern __shared__ __align__(128) char smem[];
    const uint32_t sb = smem_to_u32(smem);
    const int tid = threadIdx.x, lane = tid & 31, wid = tid >> 5;
    const int wm = wid & 1, wn = wid >> 1;
    const int bx = blockIdx.x, by = blockIdx.y;

    // stage W2 slice (128x16 f32) + b1 slice (128 f32)
    {
        const float4* s = reinterpret_cast<const float4*>(W2 + (size_t)bx * 128 * N_CLASSES);
        float4* d = reinterpret_cast<float4*>(smem + W2S_OFF);
        #pragma unroll
        for (int i = tid; i < 512; i += 256) d[i] = s[i];
        if (tid < 128) reinterpret_cast<float*>(smem + B1S_OFF)[tid] = b1[bx * 128 + tid];
    }

    float c[4][4][4];
    #pragma unroll
    for (int mi = 0; mi < 4; mi++)
        #pragma unroll
        for (int ni = 0; ni < 4; ni++)
            #pragma unroll
            for (int q = 0; q < 4; q++) c[mi][ni][q] = 0.0f;

    const int row_half = tid >> 2;       // 0..63
    const int chk = tid & 3;
    const int arow_g = by * 128;
    const int brow_g = bx * 128;

    auto load_stage = [&](int ch, int buf) {
        int kk = ch * 32;
        uint32_t sbase = sb + buf * STAGE_B;
        #pragma unroll
        for (int half = 0; half < 2; half++) {
            int row = row_half + half * 64;
            uint32_t soff = row * 64 + ((chk ^ (row & 3)) << 4);
            size_t goff = (size_t)row * IN_DIM + kk + chk * 8;
            CP_ASYNC16(sbase +    0 + soff, g_a_hi  + (size_t)arow_g * IN_DIM + goff);
            CP_ASYNC16(sbase + 8192 + soff, g_bt_hi + (size_t)brow_g * IN_DIM + goff);
        }
        CP_COMMIT();
    };

    load_stage(0, 0);
    load_stage(1, 1);

    #pragma unroll 3
    for (int ch = 0; ch < KCHUNK; ch++) {
        if (ch + 2 < KCHUNK) { CP_WAIT(1); } else { CP_WAIT(0); }
        __syncthreads();
        if (ch + 2 < KCHUNK) load_stage(ch + 2, (ch + 2) % 3);

        uint32_t aHB = sb + (ch % 3) * STAGE_B;
        uint32_t bHB = aHB + 8192;

        #pragma unroll
        for (int kk = 0; kk < 2; kk++) {
            uint32_t a[4][4], bh[4][2];
            int arow = wm * 64 + (lane & 15);
            int akc = kk * 2 + (lane >> 4);
            #pragma unroll
            for (int mi = 0; mi < 4; mi++) {
                int row = arow + mi * 16;
                ldsm4(a[mi], aHB + row * 64 + ((akc ^ (row & 3)) << 4));
            }
            int bnl = (lane & 7) + ((lane >> 4) << 3);
            int bkc = kk * 2 + ((lane >> 3) & 1);
            #pragma unroll
            for (int nn = 0; nn < 2; nn++) {
                int n = wn * 32 + nn * 16 + bnl;
                uint32_t t[4];
                ldsm4(t, bHB + n * 64 + ((bkc ^ (n & 3)) << 4));
                bh[nn * 2][0] = t[0]; bh[nn * 2][1] = t[1];
                bh[nn * 2 + 1][0] = t[2]; bh[nn * 2 + 1][1] = t[3];
            }
            #pragma unroll
            for (int mi = 0; mi < 4; mi++)
                #pragma unroll
                for (int ni = 0; ni < 4; ni++)
                    mma16816(c[mi][ni], a[mi], bh[ni]);
        }
    }

    // epilogue: stage h to smem, then h @ W2 slice -> atomic logits
    __syncthreads();
    float* h = reinterpret_cast<float*>(smem);
    const float* b1s = reinterpret_cast<const float*>(smem + B1S_OFF);
    #pragma unroll
    for (int mi = 0; mi < 4; mi++) {
        int r0 = wm * 64 + mi * 16 + (lane >> 2);
        #pragma unroll
        for (int ni = 0; ni < 4; ni++) {
            int n = wn * 32 + ni * 8 + (lane & 3) * 2;
            *reinterpret_cast<float2*>(&h[r0 * H_STRIDE + n]) =
                make_float2(c[mi][ni][0], c[mi][ni][1]);
            *reinterpret_cast<float2*>(&h[(r0 + 8) * H_STRIDE + n]) =
                make_float2(c[mi][ni][2], c[mi][ni][3]);
        }
    }
    __syncthreads();
    {
        int r = tid >> 1;
        int cg = (tid & 1) * 8;
        const float* w2s = reinterpret_cast<const float*>(smem + W2S_OFF);
        float acc[8];
        #pragma unroll
        for (int q = 0; q < 8; q++) acc[q] = 0.0f;
        #pragma unroll 4
        for (int n = 0; n < 128; n++) {
            float hv = fmaxf(h[r * H_STRIDE + n] + b1s[n], 0.0f);
            const float4* w = reinterpret_cast<const float4*>(w2s + n * N_CLASSES + cg);
            float4 w0 = w[0], w1 = w[1];
            acc[0] += hv * w0.x; acc[1] += hv * w0.y;
            acc[2] += hv * w0.z; acc[3] += hv * w0.w;
            acc[4] += hv * w1.x; acc[5] += hv * w1.y;
            acc[6] += hv * w1.z; acc[7] += hv * w1.w;
        }
        float* lg = &g_logits[(by * 128 + r) * N_CLASSES + cg];
        #pragma unroll
        for (int q = 0; q < 8; q++) atomicAdd(&lg[q], acc[q]);
    }
}

// ---- log_softmax over 16 classes ----
__global__ void k_lsm(const float* __restrict__ b2, float* __restrict__ out) {
    int t = blockIdx.x * blockDim.x + threadIdx.x;
    if (t >= N_NODES * N_CLASSES) return;
    int c = t & 15;
    float v = g_logits[t] + b2[c];
    float m = v;
    #pragma unroll
    for (int k = 8; k > 0; k >>= 1)
        m = fmaxf(m, __shfl_xor_sync(0xffffffffu, m, k, 16));
    float s = __expf(v - m);
    #pragma unroll
    for (int k = 8; k > 0; k >>= 1)
        s += __shfl_xor_sync(0xffffffffu, s, k, 16);
    out[t] = v - m - __logf(s);
}

// ---- eager module load ----
namespace {
struct EagerLoad {
    EagerLoad() {
        void* p = nullptr;
        cudaGetSymbolAddress(&p, g_logits);
        cudaGetSymbolAddress(&p, g_dinv);
        cudaGetSymbolAddress(&p, g_is64);
        cudaGetSymbolAddress(&p, g_cnt);
        cudaGetSymbolAddress(&p, g_off);
        cudaGetSymbolAddress(&p, g_cursor);
        cudaGetSymbolAddress(&p, g_csr_src);
        cudaGetSymbolAddress(&p, g_a_hi);
        cudaGetSymbolAddress(&p, g_bt_hi);
        cudaFuncAttributes a;
        cudaFuncGetAttributes(&a, k_prep_all);
        cudaFuncGetAttributes(&a, k_hist);
        cudaFuncGetAttributes(&a, k_scan);
        cudaFuncGetAttributes(&a, k_fill);
        cudaFuncGetAttributes(&a, k_gather);
        cudaFuncGetAttributes(&a, k_gemm_mma);
        cudaFuncGetAttributes(&a, k_lsm);
        cudaFuncSetAttribute(k_gemm_mma, cudaFuncAttributeMaxDynamicSharedMemorySize, SMEM_TOTAL);
    }
};
EagerLoad g_eager_load;
}

extern "C" void kernel_launch(void* const* d_in, const int* in_sizes, int n_in,
                              void* d_out, int out_size) {
    const float* x  = (const float*)d_in[0];
    const void*  ei = d_in[1];                 // [2, E], int32 OR int64 (detected)
    const float* W1 = (const float*)d_in[2];
    const float* b1 = (const float*)d_in[3];
    const float* W2 = (const float*)d_in[4];
    const float* b2 = (const float*)d_in[5];
    float* out = (float*)d_out;

    k_prep_all<<<3201, 256>>>(W1, (const int*)ei);
    k_hist<<<(N_EDGES + 255) / 256, 256>>>(ei);
    k_scan<<<1, 1024>>>();
    k_fill<<<(N_EDGES + 255) / 256, 256>>>(ei);
    k_gather<<<N_NODES / 8, 256>>>(x);

    cudaFuncSetAttribute(k_gemm_mma, cudaFuncAttributeMaxDynamicSharedMemorySize, SMEM_TOTAL);
    k_gemm_mma<<<dim3(HIDDEN / 128, N_NODES / 128), 256, SMEM_TOTAL>>>(b1, W2);
    k_lsm<<<(N_NODES * N_CLASSES + 255) / 256, 256>>>(b2, out);
}